// round 13
// baseline (speedup 1.0000x reference)
#include <cuda_runtime.h>
#include <cuda_bf16.h>
#include <math.h>
#include <float.h>
#include <stdint.h>

// Problem constants
#define BB 4
#define TT 8192
#define SS 4096
#define DD 256
#define GG 512
#define KK 8
#define ROWS (BB*TT)        // 32768
#define NREAL 259           // template(3) + local(256); global folded into bias
#define KPAD1 288           // 9 * 32
#define NG1 384             // 256 (W1) + 128 (M1); skip branch folded out
#define MATOFF (ROWS*3)     // offset of mat in out
#define NIB (ROWS/4)        // 8192 ni blocks in build_ni

// ---------------- scratch (device globals; no allocation) ----------------
__device__ __align__(128) int   g_idx[ROWS * KK];
__device__ __align__(128) float g_d2 [ROWS * KK];
__device__ __align__(128) __nv_bfloat16 g_ni_hi[(size_t)ROWS * KPAD1];
__device__ __align__(128) __nv_bfloat16 g_ni_lo[(size_t)ROWS * KPAD1];
__device__ __align__(128) __nv_bfloat16 g_w1t_hi[NG1 * KPAD1];
__device__ __align__(128) __nv_bfloat16 g_w1t_lo[NG1 * KPAD1];
__device__ __align__(128) __nv_bfloat16 g_w2t_hi[256 * 256];
__device__ __align__(128) float g_bias_eff[BB * NG1];  // bias + gfeat@W_global
__device__ __align__(128) float g_wso[771 * 3];        // Ws @ Wo (fp32 exact)
__device__ __align__(128) float g_disp0[BB * 3];       // 0.3*(bo + (bs+gs).Wo)
__device__ __align__(128) __nv_bfloat16 g_h1hi[(size_t)ROWS * 256];
__device__ __align__(128) float g_m1f[(size_t)ROWS * 128];

// =================== helpers =============================================
__device__ __forceinline__ uint32_t smem_to_u32(const void* p) {
    uint32_t a;
    asm("{ .reg .u64 t; cvta.to.shared.u64 t, %1; cvt.u32.u64 %0, t; }" : "=r"(a) : "l"(p));
    return a;
}
__device__ __forceinline__ void ldsm4(uint32_t* r, uint32_t addr) {
    asm volatile("ldmatrix.sync.aligned.m8n8.x4.shared.b16 {%0,%1,%2,%3}, [%4];"
        : "=r"(r[0]), "=r"(r[1]), "=r"(r[2]), "=r"(r[3]) : "r"(addr));
}
__device__ __forceinline__ void mma_bf16(float* c, const uint32_t* a, const uint32_t* b) {
    asm volatile("mma.sync.aligned.m16n8k16.row.col.f32.bf16.bf16.f32 "
        "{%0,%1,%2,%3}, {%4,%5,%6,%7}, {%8,%9}, {%0,%1,%2,%3};"
        : "+f"(c[0]), "+f"(c[1]), "+f"(c[2]), "+f"(c[3])
        : "r"(a[0]), "r"(a[1]), "r"(a[2]), "r"(a[3]), "r"(b[0]), "r"(b[1]));
}
#define CP_ASYNC16(dst, src) \
    asm volatile("cp.async.cg.shared.global [%0], [%1], 16;" :: "r"(dst), "l"(src))
#define CP_COMMIT()  asm volatile("cp.async.commit_group;" ::: "memory")
#define CP_WAIT(n)   asm volatile("cp.async.wait_group %0;" :: "n"(n) : "memory")

__device__ __forceinline__ uint32_t swz64(uint32_t off) {
    return off ^ (((off >> 7) & 3u) << 4);
}
__device__ __forceinline__ void bf16split(float v, __nv_bfloat16& h, __nv_bfloat16& l) {
    h = __float2bfloat16(v);
    l = __float2bfloat16(v - __bfloat162float(h));
}

// ---------------- prep1: wso | bias_eff | disp0 (disjoint block ranges) --
__global__ void prep1_kernel(const float* __restrict__ Ws,
                             const float* __restrict__ Wo,
                             const float* __restrict__ W1,
                             const float* __restrict__ M1,
                             const float* __restrict__ b1,
                             const float* __restrict__ mb1,
                             const float* __restrict__ gfeat,
                             const float* __restrict__ bs,
                             const float* __restrict__ bo)
{
    const int bx = blockIdx.x, tid = threadIdx.x;
    if (bx < 10) {                        // wso = Ws @ Wo (771 x 3)
        int idx = bx * 256 + tid;
        if (idx < 771 * 3) {
            int k = idx / 3, o = idx % 3;
            float acc = 0.f;
#pragma unroll 8
            for (int h = 0; h < 256; h++)
                acc = fmaf(Ws[k*256 + h], Wo[h*3 + o], acc);
            g_wso[idx] = acc;
        }
    } else if (bx < 16) {                 // bias_eff (4 x 384)
        int idx = (bx - 10) * 256 + tid;
        if (idx < BB * NG1) {
            int b = idx / NG1, n = idx % NG1;
            const float* gf = gfeat + b * GG;
            float acc;
            if (n < 256) {
                acc = b1[n];
                const float* w = W1 + 259*256 + n;
#pragma unroll 8
                for (int j = 0; j < GG; j++) acc = fmaf(gf[j], w[j*256], acc);
            } else {
                acc = mb1[n-256];
                const float* w = M1 + 259*128 + (n - 256);
#pragma unroll 8
                for (int j = 0; j < GG; j++) acc = fmaf(gf[j], w[j*128], acc);
            }
            g_bias_eff[idx] = acc;
        }
    } else {                              // disp0
        __shared__ float sv[BB][256];
        const int h = tid;
#pragma unroll
        for (int b = 0; b < BB; b++) {
            float acc = bs[h];
            const float* gf = gfeat + b * GG;
#pragma unroll 8
            for (int j = 0; j < GG; j++)
                acc = fmaf(gf[j], Ws[(NREAL + j)*256 + h], acc);
            sv[b][h] = acc;
        }
        __syncthreads();
        if (tid < BB * 3) {
            int b = tid / 3, o = tid % 3;
            float acc = bo[o];
#pragma unroll 8
            for (int hh = 0; hh < 256; hh++)
                acc = fmaf(sv[b][hh], Wo[hh*3 + o], acc);
            g_disp0[tid] = 0.3f * acc;
        }
    }
}

// ---------------- w1pack: transpose+split W1/M1 to bf16 hi/lo ------------
__global__ void w1pack_kernel(const float* __restrict__ W1,
                              const float* __restrict__ M1)
{
    int idx = blockIdx.x * 256 + threadIdx.x;
    if (idx < NG1 * KPAD1) {
        int n = idx / KPAD1, k = idx % KPAD1;
        float v = 0.f;
        if (k < NREAL) {
            if (n < 256) v = W1[k*256 + n];
            else         v = M1[k*128 + (n-256)];
        }
        __nv_bfloat16 h, l; bf16split(v, h, l);
        g_w1t_hi[idx] = h; g_w1t_lo[idx] = l;
    }
}

// ---------------- w2pack: transpose W2 to bf16 ---------------------------
__global__ void w2pack_kernel(const float* __restrict__ W2)
{
    int idx = blockIdx.x * 256 + threadIdx.x;
    if (idx < 256 * 256) {
        int n = idx / 256, k = idx % 256;
        g_w2t_hi[idx] = __float2bfloat16(W2[k*256 + n]);
    }
}

// ---------------- KNN: 8-way surf split, 32 points/block -----------------
// thread = (chunk c = tid>>5, point p = tid&31). Key e = |s|^2 - 2 t.s.
// Candidate arrays use stride-32 layout: write (c*8+q)*32+p (consecutive p),
// read s*32+p (bank p for all s) -> conflict-free both ways.
__global__ void __launch_bounds__(256) knn_kernel(
    const float* __restrict__ tmpl,
    const float* __restrict__ surf)
{
    __shared__ float4 ss[2048];          // 32 KB (xyz, |s|^2)
    __shared__ float  ce[64 * 32];       // 8 KB keys
    __shared__ int    ci[64 * 32];       // 8 KB indices
    const int tid = threadIdx.x;
    const int c   = tid >> 5;            // chunk 0..7
    const int p   = tid & 31;            // point-in-block
    const int b   = blockIdx.y;
    const int row = b * TT + blockIdx.x * 32 + p;

    const float tx = tmpl[row*3+0];
    const float ty = tmpl[row*3+1];
    const float tz = tmpl[row*3+2];
    const float nx2 = -2.f*tx, ny2 = -2.f*ty, nz2 = -2.f*tz;
    const float tt2 = fmaf(tx,tx, fmaf(ty,ty, tz*tz));

    float be[KK]; int bi[KK];
#pragma unroll
    for (int q = 0; q < KK; q++) { be[q] = FLT_MAX; bi[q] = 0; }
    const float* sb = surf + (size_t)b * SS * 3;

    for (int tile = 0; tile < 2; tile++) {
        __syncthreads();
        for (int i = tid; i < 2048; i += 256) {
            int sp = tile * 2048 + i;
            float x = sb[sp*3+0], y = sb[sp*3+1], z = sb[sp*3+2];
            ss[i] = make_float4(x, y, z, fmaf(x,x, fmaf(y,y, z*z)));
        }
        __syncthreads();
        const int j0 = c * 256;
#pragma unroll 4
        for (int j = j0; j < j0 + 256; j++) {
            float4 q4 = ss[j];
            float e = fmaf(nx2, q4.x, fmaf(ny2, q4.y, fmaf(nz2, q4.z, q4.w)));
            if (e < be[KK-1]) {
                float v = e; int vi = tile * 2048 + j;
#pragma unroll
                for (int q = 0; q < KK; q++) {
                    if (v < be[q]) {
                        float tv = be[q]; int ti = bi[q];
                        be[q] = v; bi[q] = vi; v = tv; vi = ti;
                    }
                }
            }
        }
    }
    // publish per-chunk top-8 (conflict-free: consecutive p per (c,q))
#pragma unroll
    for (int q = 0; q < KK; q++) {
        ce[(c*KK + q)*32 + p] = be[q];
        ci[(c*KK + q)*32 + p] = bi[q];
    }
    __syncthreads();
    // merge 64 candidates per point (threads 0..31; bank-p reads)
    if (tid < 32) {
        float me[KK]; int mi[KK];
#pragma unroll
        for (int q = 0; q < KK; q++) { me[q] = FLT_MAX; mi[q] = 0; }
#pragma unroll 4
        for (int s = 0; s < 64; s++) {
            float v = ce[s*32 + tid];
            if (v < me[KK-1]) {
                int vi = ci[s*32 + tid];
#pragma unroll
                for (int q = 0; q < KK; q++) {
                    if (v < me[q]) {
                        float tv = me[q]; int ti = mi[q];
                        me[q] = v; mi[q] = vi;
                        v = tv; vi = ti;
                    }
                }
            }
        }
        const int orow = b * TT + blockIdx.x * 32 + tid;
#pragma unroll
        for (int q = 0; q < KK; q++) {
            g_d2 [orow*KK+q] = fmaxf(me[q] + tt2, 0.f);
            g_idx[orow*KK+q] = mi[q];
        }
    }
}

// ---------------- build_ni + exact skip-dot store ------------------------
__global__ void __launch_bounds__(256) build_ni_kernel(
    const float* __restrict__ tmpl,
    const float* __restrict__ pfeat,
    float* __restrict__ out)
{
    __shared__ float sw [4][KK];
    __shared__ int   sid[4][KK];
    __shared__ float srow[4][KPAD1];
    __shared__ float swso[NREAL * 3];
    const int tid  = threadIdx.x;
    const int row0 = blockIdx.x * 4;

    for (int i = tid; i < NREAL * 3; i += 256) swso[i] = g_wso[i];

    if (tid < 32) {
        int rloc = tid >> 3, k = tid & 7;
        int row = row0 + rloc;
        sid[rloc][k] = g_idx[row*KK + k];
        float d = sqrtf(g_d2[row*KK + k]);
        float w = 1.f / (d + 1e-8f);
        float s = w;
#pragma unroll
        for (int o = 1; o < 8; o <<= 1)
            s += __shfl_xor_sync(0xffffffffu, s, o);
        sw[rloc][k] = w / s;
    }
    if (tid >= 32 && tid < 44) {
        int q = tid - 32; int rloc = q / 3, c = q % 3;
        srow[rloc][c] = tmpl[(row0 + rloc)*3 + c];
    }
    if (tid >= 64 && tid < 64 + 4*(KPAD1 - NREAL)) {
        int q = tid - 64; int rloc = q / (KPAD1 - NREAL), c = q % (KPAD1 - NREAL);
        srow[rloc][NREAL + c] = 0.f;
    }
    __syncthreads();

    {   // coalesced float4 gather, 64 threads per row
        const int rloc = tid >> 6, c4 = tid & 63;
        const int b = (row0 + rloc) >> 13;
        const float* pfb = pfeat + (size_t)b * SS * DD;
        float4 acc = make_float4(0.f, 0.f, 0.f, 0.f);
#pragma unroll
        for (int k = 0; k < KK; k++) {
            const float w = sw[rloc][k];
            const float4 v = *(const float4*)(pfb + (size_t)sid[rloc][k]*DD + c4*4);
            acc.x = fmaf(w, v.x, acc.x);
            acc.y = fmaf(w, v.y, acc.y);
            acc.z = fmaf(w, v.z, acc.z);
            acc.w = fmaf(w, v.w, acc.w);
        }
        srow[rloc][3 + c4*4 + 0] = acc.x;
        srow[rloc][3 + c4*4 + 1] = acc.y;
        srow[rloc][3 + c4*4 + 2] = acc.z;
        srow[rloc][3 + c4*4 + 3] = acc.w;
    }
    __syncthreads();

    // exact skip: warp w handles row rloc=w; STORE disp0 + 0.3*dot
    const int w = tid >> 5, lane = tid & 31;
    if (w < 4) {
        float d0 = 0.f, d1 = 0.f, d2 = 0.f;
        for (int c = lane; c < NREAL; c += 32) {
            const float v = srow[w][c];
            d0 = fmaf(v, swso[c*3+0], d0);
            d1 = fmaf(v, swso[c*3+1], d1);
            d2 = fmaf(v, swso[c*3+2], d2);
        }
#pragma unroll
        for (int o = 16; o > 0; o >>= 1) {
            d0 += __shfl_xor_sync(0xffffffffu, d0, o);
            d1 += __shfl_xor_sync(0xffffffffu, d1, o);
            d2 += __shfl_xor_sync(0xffffffffu, d2, o);
        }
        if (lane == 0) {
            const int row = row0 + w;
            const int bb  = row >> 13;
            out[row*3+0] = g_disp0[bb*3+0] + 0.3f * d0;
            out[row*3+1] = g_disp0[bb*3+1] + 0.3f * d1;
            out[row*3+2] = g_disp0[bb*3+2] + 0.3f * d2;
        }
    }

    // pack to bf16 hi/lo, 8B stores
    for (int p = tid; p < 4 * (KPAD1/4); p += 256) {
        int rloc = p / (KPAD1/4), q = p % (KPAD1/4);
        __nv_bfloat16 hv[4], lv[4];
#pragma unroll
        for (int s = 0; s < 4; s++)
            bf16split(srow[rloc][q*4 + s], hv[s], lv[s]);
        size_t base = (size_t)(row0 + rloc) * KPAD1 + q*4;
        *(uint2*)&g_ni_hi[base] = *(uint2*)hv;
        *(uint2*)&g_ni_lo[base] = *(uint2*)lv;
    }
}

// =============== mma.sync bf16 GEMM (128x64, BK=32) ======================
// MODE 0: GEMM1  A=ni hi/lo (K=288), B=w1t hi/lo (3-term comp) -> h1/m1
// MODE 1: GEMM2a A=h1 bf16 (K=256),  B=w2t hi (1-term) -> disp atomics
#define A_TILE_B 8192        // 128 rows x 64 bytes
#define B_TILE_B 4096        // 64 rows x 64 bytes

template<int MODE>
__global__ void __launch_bounds__(256, 3) mma_gemm(const float* __restrict__ biasext,
                                                   const float* __restrict__ Wo,
                                                   float* __restrict__ out)
{
    constexpr int  KTOT = (MODE == 0) ? KPAD1 : 256;
    constexpr int  NCH  = KTOT / 32;
    constexpr bool COMP = (MODE == 0);

    __shared__ __align__(128) __nv_bfloat16 sAhi[2][A_TILE_B/2];
    __shared__ __align__(128) __nv_bfloat16 sAlo[2][A_TILE_B/2];
    __shared__ __align__(128) __nv_bfloat16 sBhi[2][B_TILE_B/2];
    __shared__ __align__(128) __nv_bfloat16 sBlo[2][B_TILE_B/2];

    const int tid  = threadIdx.x;
    const int wid  = tid >> 5;
    const int lane = tid & 31;
    const int m0 = blockIdx.y * 128;
    const int n0 = blockIdx.x * 64;

    const __nv_bfloat16 *Ahi, *Alo, *Bhi, *Blo;
    const float* bias;
    if (MODE == 0) { Ahi = g_ni_hi; Alo = g_ni_lo; Bhi = g_w1t_hi; Blo = g_w1t_lo;
                     bias = g_bias_eff + (m0 >> 13) * NG1; }
    else           { Ahi = g_h1hi;  Alo = g_h1hi;  Bhi = g_w2t_hi; Blo = g_w2t_hi;
                     bias = biasext; }

    const uint32_t uAhi[2] = { smem_to_u32(sAhi[0]), smem_to_u32(sAhi[1]) };
    const uint32_t uAlo[2] = { smem_to_u32(sAlo[0]), smem_to_u32(sAlo[1]) };
    const uint32_t uBhi[2] = { smem_to_u32(sBhi[0]), smem_to_u32(sBhi[1]) };
    const uint32_t uBlo[2] = { smem_to_u32(sBlo[0]), smem_to_u32(sBlo[1]) };

    const int wm = (wid & 3) * 32;
    const int wn = (wid >> 2) * 32;

    float acc[2][4][4];
#pragma unroll
    for (int i = 0; i < 2; i++)
#pragma unroll
        for (int j = 0; j < 4; j++)
#pragma unroll
            for (int q = 0; q < 4; q++) acc[i][j][q] = 0.f;

    auto issue_stage = [&](int ch, int buf) {
        const int kc = ch * 32;
        constexpr int ACH   = COMP ? 1024 : 512;
        constexpr int NLOAD = COMP ? 6 : 3;
#pragma unroll
        for (int t = 0; t < NLOAD; t++) {
            int idx = tid + t * 256;
            if (idx < ACH) {
                int half  = COMP ? (idx >> 9) : 0;
                int sub   = idx & 511;
                int row   = sub >> 2;
                int chunk = sub & 3;
                const __nv_bfloat16* gp =
                    (half ? Alo : Ahi) + (size_t)(m0 + row) * KTOT + kc + chunk * 8;
                uint32_t off = swz64((uint32_t)(row * 64 + chunk * 16));
                CP_ASYNC16((half ? uAlo[buf] : uAhi[buf]) + off, gp);
            } else {
                int sub   = idx - ACH;
                int half  = COMP ? (sub >> 8) : 0;
                int s2    = sub & 255;
                int row   = s2 >> 2;
                int chunk = s2 & 3;
                const __nv_bfloat16* gp =
                    (half ? Blo : Bhi) + (size_t)(n0 + row) * KTOT + kc + chunk * 8;
                uint32_t off = swz64((uint32_t)(row * 64 + chunk * 16));
                CP_ASYNC16((half ? uBlo[buf] : uBhi[buf]) + off, gp);
            }
        }
        CP_COMMIT();
    };

    issue_stage(0, 0);
#pragma unroll 1
    for (int ch = 0; ch < NCH; ch++) {
        const int buf = ch & 1;
        if (ch + 1 < NCH) { issue_stage(ch + 1, buf ^ 1); CP_WAIT(1); }
        else              { CP_WAIT(0); }
        __syncthreads();

        const int lrow = (lane & 7) + ((lane >> 3) & 1) * 8;
        const int lk   = ((lane >> 4) & 1) * 8;
#pragma unroll
        for (int k16 = 0; k16 < 2; k16++) {
            const int kcol = k16 * 16 + lk;
            uint32_t bh[4][2], bl[4][2];
#pragma unroll
            for (int j2 = 0; j2 < 2; j2++) {
                uint32_t off = swz64((uint32_t)((wn + j2*16 + lrow) * 64 + kcol * 2));
                uint32_t r[4];
                ldsm4(r, uBhi[buf] + off);
                bh[j2*2][0] = r[0]; bh[j2*2+1][0] = r[1];
                bh[j2*2][1] = r[2]; bh[j2*2+1][1] = r[3];
                if (COMP) {
                    ldsm4(r, uBlo[buf] + off);
                    bl[j2*2][0] = r[0]; bl[j2*2+1][0] = r[1];
                    bl[j2*2][1] = r[2]; bl[j2*2+1][1] = r[3];
                }
            }
#pragma unroll
            for (int i = 0; i < 2; i++) {
                uint32_t af[4];
                uint32_t off = swz64((uint32_t)((wm + i*16 + lrow) * 64 + kcol * 2));
                ldsm4(af, uAhi[buf] + off);
#pragma unroll
                for (int j = 0; j < 4; j++) {
                    mma_bf16(acc[i][j], af, bh[j]);           // hi*hi
                    if (COMP) mma_bf16(acc[i][j], af, bl[j]); // hi*lo
                }
                if (COMP) {
                    ldsm4(af, uAlo[buf] + off);
#pragma unroll
                    for (int j = 0; j < 4; j++)
                        mma_bf16(acc[i][j], af, bh[j]);       // lo*hi
                }
            }
        }
        __syncthreads();
    }

    // ---- epilogue -------------------------------------------------------
    const int g     = lane >> 2;
    const int cpair = (lane & 3) * 2;
#pragma unroll
    for (int i = 0; i < 2; i++) {
#pragma unroll
        for (int half = 0; half < 2; half++) {
            const int r = m0 + wm + i*16 + g + half*8;
            if (MODE == 0) {
#pragma unroll
                for (int j = 0; j < 4; j++) {
                    const int c0 = n0 + wn + j*8 + cpair;
                    const float v0r = acc[i][j][half*2+0] + bias[c0];
                    const float v1r = acc[i][j][half*2+1] + bias[c0+1];
                    if (c0 < 256) {                 // h1: relu -> bf16
                        __nv_bfloat162 ph;
                        ph.x = __float2bfloat16(fmaxf(v0r, 0.f));
                        ph.y = __float2bfloat16(fmaxf(v1r, 0.f));
                        *(__nv_bfloat162*)&g_h1hi[(size_t)r*256 + c0] = ph;
                    } else {                        // m1: relu f32
                        float2 p; p.x = fmaxf(v0r, 0.f); p.y = fmaxf(v1r, 0.f);
                        *(float2*)&g_m1f[(size_t)r*128 + (c0-256)] = p;
                    }
                }
            } else {
                float d0 = 0.f, d1 = 0.f, d2 = 0.f;
#pragma unroll
                for (int j = 0; j < 4; j++) {
                    const int c0 = n0 + wn + j*8 + cpair;
                    float v0 = fmaxf(acc[i][j][half*2+0] + bias[c0],   0.f);
                    float v1 = fmaxf(acc[i][j][half*2+1] + bias[c0+1], 0.f);
                    d0 = fmaf(v0, Wo[c0*3+0], fmaf(v1, Wo[(c0+1)*3+0], d0));
                    d1 = fmaf(v0, Wo[c0*3+1], fmaf(v1, Wo[(c0+1)*3+1], d1));
                    d2 = fmaf(v0, Wo[c0*3+2], fmaf(v1, Wo[(c0+1)*3+2], d2));
                }
#pragma unroll
                for (int o = 1; o <= 2; o <<= 1) {
                    d0 += __shfl_xor_sync(0xffffffffu, d0, o);
                    d1 += __shfl_xor_sync(0xffffffffu, d1, o);
                    d2 += __shfl_xor_sync(0xffffffffu, d2, o);
                }
                if ((lane & 3) == 0) {
                    atomicAdd(&out[r*3+0], 0.3f * d0);
                    atomicAdd(&out[r*3+1], 0.3f * d1);
                    atomicAdd(&out[r*3+2], 0.3f * d2);
                }
            }
        }
    }
}

// ---------------- GEMM2b + mat head --------------------------------------
__global__ void gemm2b_kernel(const float* __restrict__ M2w,
                              const float* __restrict__ mb2,
                              const float* __restrict__ M3,
                              const float* __restrict__ mb3,
                              float* __restrict__ out)
{
    constexpr int BM=128, BN=64, BK=16, TM=8, TN=4, THREADS=256;
    __shared__ __align__(16) float As[BK*BM];
    __shared__ __align__(16) float Bs[BK*BN];
    const int tid  = threadIdx.x;
    const int row0 = blockIdx.x * BM;
    const int tm0  = (tid / (BN/TN)) * TM;
    const int tn0  = (tid % (BN/TN)) * TN;
    float4 pa[2], pb[1];

    auto loadg = [&](int k0) {
#pragma unroll
        for (int i = 0; i < 2; i++) {
            int idx = tid + i*THREADS; int m = idx / 4; int kv = idx % 4;
            pa[i] = *(const float4*)(g_m1f + (size_t)(row0+m)*128 + k0 + kv*4);
        }
        { int kr = tid / 16; int nv = tid % 16;
          pb[0] = *(const float4*)(M2w + (size_t)(k0 + kr)*64 + nv*4); }
    };
    auto stage = [&]() {
#pragma unroll
        for (int i = 0; i < 2; i++) {
            int idx = tid + i*THREADS; int m = idx / 4; int kv = idx % 4;
            As[(kv*4+0)*BM+m]=pa[i].x; As[(kv*4+1)*BM+m]=pa[i].y;
            As[(kv*4+2)*BM+m]=pa[i].z; As[(kv*4+3)*BM+m]=pa[i].w;
        }
        { int kr = tid / 16; int nv = tid % 16;
          *(float4*)&Bs[kr*BN + nv*4] = pb[0]; }
    };

    float acc[TM][TN];
#pragma unroll
    for (int i=0;i<TM;i++)
#pragma unroll
        for (int j=0;j<TN;j++) acc[i][j]=0.f;

    loadg(0);
#pragma unroll 1
    for (int t = 0; t < 128/BK; t++) {
        __syncthreads(); stage(); __syncthreads();
        if (t+1 < 128/BK) loadg((t+1)*BK);
#pragma unroll
        for (int kk = 0; kk < BK; kk++) {
            float af[TM], bf[TN];
#pragma unroll
            for (int i=0;i<TM/4;i++) *(float4*)&af[i*4] = *(const float4*)&As[kk*BM+tm0+i*4];
            *(float4*)&bf[0] = *(const float4*)&Bs[kk*BN+tn0];
#pragma unroll
            for (int i=0;i<TM;i++)
#pragma unroll
                for (int j=0;j<TN;j++) acc[i][j] = fmaf(af[i], bf[j], acc[i][j]);
        }
    }

    float mv[TM];
#pragma unroll
    for (int i=0;i<TM;i++) {
        float m = 0.f;
#pragma unroll
        for (int j=0;j<TN;j++) {
            int n = tn0 + j;
            m = fmaf(fmaxf(acc[i][j] + mb2[n], 0.f), M3[n], m);
        }
        mv[i] = m;
    }
#pragma unroll
    for (int o = 1; o <= 8; o <<= 1)
#pragma unroll
        for (int i=0;i<TM;i++)
            mv[i] += __shfl_xor_sync(0xffffffffu, mv[i], o);
    if ((tid & 15) == 0) {
        const float b3 = mb3[0];
#pragma unroll
        for (int i=0;i<TM;i++) {
            float x = mv[i] + b3;
            out[MATOFF + row0 + tm0 + i] = 1.f / (1.f + expf(-x));
        }
    }
}

// --------------------------------- launch --------------------------------
extern "C" void kernel_launch(void* const* d_in, const int* in_sizes, int n_in,
                              void* d_out, int out_size)
{
    const float* tmpl  = (const float*)d_in[0];
    const float* surf  = (const float*)d_in[1];
    const float* gfeat = (const float*)d_in[2];
    const float* pfeat = (const float*)d_in[3];
    const float* W1 = (const float*)d_in[4];
    const float* b1 = (const float*)d_in[5];
    const float* W2 = (const float*)d_in[6];
    const float* b2 = (const float*)d_in[7];
    const float* Ws = (const float*)d_in[8];
    const float* bs = (const float*)d_in[9];
    const float* Wo = (const float*)d_in[10];
    const float* bo = (const float*)d_in[11];
    const float* M1 = (const float*)d_in[12];
    const float* mb1 = (const float*)d_in[13];
    const float* M2 = (const float*)d_in[14];
    const float* mb2 = (const float*)d_in[15];
    const float* M3 = (const float*)d_in[16];
    const float* mb3 = (const float*)d_in[17];
    float* out = (float*)d_out;

    // 1-3: precompute (independent of KNN)
    prep1_kernel<<<17, 256>>>(Ws, Wo, W1, M1, b1, mb1, gfeat, bs, bo);
    w1pack_kernel<<<(NG1*KPAD1 + 255)/256, 256>>>(W1, M1);
    w2pack_kernel<<<256, 256>>>(W2);
    // 4: KNN (8-way split)  <- profiled slot
    knn_kernel<<<dim3(TT/32, BB), 256>>>(tmpl, surf);
    // 5: ni build + skip-dot store
    build_ni_kernel<<<NIB, 256>>>(tmpl, pfeat, out);
    // 6: GEMM1  [32768 x 288] @ [288 x 384]
    mma_gemm<0><<<dim3(NG1/64, ROWS/128), 256>>>(nullptr, nullptr, nullptr);
    // 7: GEMM2a + disp head (atomic, 1024 blocks)
    mma_gemm<1><<<dim3(256/64, ROWS/128), 256>>>(b2, Wo, out);
    // 8: GEMM2b + mat head
    gemm2b_kernel<<<ROWS/128, 256>>>(M2, mb2, M3, mb3, out);
}

// round 14
// speedup vs baseline: 1.0403x; 1.0403x over previous
#include <cuda_runtime.h>
#include <cuda_bf16.h>
#include <math.h>
#include <float.h>
#include <stdint.h>

// Problem constants
#define BB 4
#define TT 8192
#define SS 4096
#define DD 256
#define GG 512
#define KK 8
#define ROWS (BB*TT)        // 32768
#define NREAL 259           // template(3) + local(256); global folded into bias
#define KPAD1 288           // 9 * 32
#define NG1 384             // 256 (W1) + 128 (M1); skip branch folded out
#define MATOFF (ROWS*3)     // offset of mat in out
#define NIB (ROWS/4)        // 8192 ni blocks in build_ni

// ---------------- scratch (device globals; no allocation) ----------------
__device__ __align__(128) int   g_idx[ROWS * KK];
__device__ __align__(128) float g_d2 [ROWS * KK];
__device__ __align__(128) __nv_bfloat16 g_ni_hi[(size_t)ROWS * KPAD1];
__device__ __align__(128) __nv_bfloat16 g_ni_lo[(size_t)ROWS * KPAD1];
__device__ __align__(128) __nv_bfloat16 g_w1t_hi[NG1 * KPAD1];
__device__ __align__(128) __nv_bfloat16 g_w1t_lo[NG1 * KPAD1];
__device__ __align__(128) __nv_bfloat16 g_w2t_hi[256 * 256];
__device__ __align__(128) float g_bias_eff[BB * NG1];  // bias + gfeat@W_global
__device__ __align__(128) float g_wso[771 * 3];        // Ws @ Wo (fp32 exact)
__device__ __align__(128) float g_disp0[BB * 3];       // 0.3*(bo + (bs+gs).Wo)
__device__ __align__(128) __nv_bfloat16 g_h1hi[(size_t)ROWS * 256];
__device__ __align__(128) float g_m1f[(size_t)ROWS * 128];

// =================== helpers =============================================
__device__ __forceinline__ uint32_t smem_to_u32(const void* p) {
    uint32_t a;
    asm("{ .reg .u64 t; cvta.to.shared.u64 t, %1; cvt.u32.u64 %0, t; }" : "=r"(a) : "l"(p));
    return a;
}
__device__ __forceinline__ void ldsm4(uint32_t* r, uint32_t addr) {
    asm volatile("ldmatrix.sync.aligned.m8n8.x4.shared.b16 {%0,%1,%2,%3}, [%4];"
        : "=r"(r[0]), "=r"(r[1]), "=r"(r[2]), "=r"(r[3]) : "r"(addr));
}
__device__ __forceinline__ void mma_bf16(float* c, const uint32_t* a, const uint32_t* b) {
    asm volatile("mma.sync.aligned.m16n8k16.row.col.f32.bf16.bf16.f32 "
        "{%0,%1,%2,%3}, {%4,%5,%6,%7}, {%8,%9}, {%0,%1,%2,%3};"
        : "+f"(c[0]), "+f"(c[1]), "+f"(c[2]), "+f"(c[3])
        : "r"(a[0]), "r"(a[1]), "r"(a[2]), "r"(a[3]), "r"(b[0]), "r"(b[1]));
}
#define CP_ASYNC16(dst, src) \
    asm volatile("cp.async.cg.shared.global [%0], [%1], 16;" :: "r"(dst), "l"(src))
#define CP_COMMIT()  asm volatile("cp.async.commit_group;" ::: "memory")
#define CP_WAIT(n)   asm volatile("cp.async.wait_group %0;" :: "n"(n) : "memory")

__device__ __forceinline__ uint32_t swz64(uint32_t off) {
    return off ^ (((off >> 7) & 3u) << 4);
}
__device__ __forceinline__ void bf16split(float v, __nv_bfloat16& h, __nv_bfloat16& l) {
    h = __float2bfloat16(v);
    l = __float2bfloat16(v - __bfloat162float(h));
}

// ---------------- prep1: wso | bias_eff | disp0 (disjoint block ranges) --
__global__ void prep1_kernel(const float* __restrict__ Ws,
                             const float* __restrict__ Wo,
                             const float* __restrict__ W1,
                             const float* __restrict__ M1,
                             const float* __restrict__ b1,
                             const float* __restrict__ mb1,
                             const float* __restrict__ gfeat,
                             const float* __restrict__ bs,
                             const float* __restrict__ bo)
{
    const int bx = blockIdx.x, tid = threadIdx.x;
    if (bx < 10) {                        // wso = Ws @ Wo (771 x 3)
        int idx = bx * 256 + tid;
        if (idx < 771 * 3) {
            int k = idx / 3, o = idx % 3;
            float acc = 0.f;
#pragma unroll 8
            for (int h = 0; h < 256; h++)
                acc = fmaf(Ws[k*256 + h], Wo[h*3 + o], acc);
            g_wso[idx] = acc;
        }
    } else if (bx < 16) {                 // bias_eff (4 x 384)
        int idx = (bx - 10) * 256 + tid;
        if (idx < BB * NG1) {
            int b = idx / NG1, n = idx % NG1;
            const float* gf = gfeat + b * GG;
            float acc;
            if (n < 256) {
                acc = b1[n];
                const float* w = W1 + 259*256 + n;
#pragma unroll 8
                for (int j = 0; j < GG; j++) acc = fmaf(gf[j], w[j*256], acc);
            } else {
                acc = mb1[n-256];
                const float* w = M1 + 259*128 + (n - 256);
#pragma unroll 8
                for (int j = 0; j < GG; j++) acc = fmaf(gf[j], w[j*128], acc);
            }
            g_bias_eff[idx] = acc;
        }
    } else {                              // disp0
        __shared__ float sv[BB][256];
        const int h = tid;
#pragma unroll
        for (int b = 0; b < BB; b++) {
            float acc = bs[h];
            const float* gf = gfeat + b * GG;
#pragma unroll 8
            for (int j = 0; j < GG; j++)
                acc = fmaf(gf[j], Ws[(NREAL + j)*256 + h], acc);
            sv[b][h] = acc;
        }
        __syncthreads();
        if (tid < BB * 3) {
            int b = tid / 3, o = tid % 3;
            float acc = bo[o];
#pragma unroll 8
            for (int hh = 0; hh < 256; hh++)
                acc = fmaf(sv[b][hh], Wo[hh*3 + o], acc);
            g_disp0[tid] = 0.3f * acc;
        }
    }
}

// ---------------- w1pack: transpose+split W1/M1 to bf16 hi/lo ------------
__global__ void w1pack_kernel(const float* __restrict__ W1,
                              const float* __restrict__ M1)
{
    int idx = blockIdx.x * 256 + threadIdx.x;
    if (idx < NG1 * KPAD1) {
        int n = idx / KPAD1, k = idx % KPAD1;
        float v = 0.f;
        if (k < NREAL) {
            if (n < 256) v = W1[k*256 + n];
            else         v = M1[k*128 + (n-256)];
        }
        __nv_bfloat16 h, l; bf16split(v, h, l);
        g_w1t_hi[idx] = h; g_w1t_lo[idx] = l;
    }
}

// ---------------- w2pack: transpose W2 to bf16 ---------------------------
__global__ void w2pack_kernel(const float* __restrict__ W2)
{
    int idx = blockIdx.x * 256 + threadIdx.x;
    if (idx < 256 * 256) {
        int n = idx / 256, k = idx % 256;
        g_w2t_hi[idx] = __float2bfloat16(W2[k*256 + n]);
    }
}

// ---------------- KNN: unchunked scan, 4-wide software pipeline ----------
// One thread per template point scans all 4096 surf points (lowest possible
// warp-amplified insert rate ~24%). 4 candidates loaded per iter for MLP.
// Key e = |s|^2 - 2 t.s (monotone in d2); d2 = max(e + |t|^2, 0) at end.
__global__ void __launch_bounds__(128) knn_kernel(
    const float* __restrict__ tmpl,
    const float* __restrict__ surf)
{
    __shared__ float4 ss[2048];          // 32 KB (xyz, |s|^2)
    const int b   = blockIdx.y;
    const int t   = blockIdx.x * 128 + threadIdx.x;
    const int row = b * TT + t;

    const float tx = tmpl[row*3+0];
    const float ty = tmpl[row*3+1];
    const float tz = tmpl[row*3+2];
    const float nx2 = -2.f*tx, ny2 = -2.f*ty, nz2 = -2.f*tz;
    const float tt2 = fmaf(tx,tx, fmaf(ty,ty, tz*tz));

    float be[KK]; int bi[KK];
#pragma unroll
    for (int q = 0; q < KK; q++) { be[q] = FLT_MAX; bi[q] = 0; }
    const float* sb = surf + (size_t)b * SS * 3;

    auto insert = [&](float v, int vi) {
#pragma unroll
        for (int q = 0; q < KK; q++) {
            if (v < be[q]) {
                float tv = be[q]; int ti = bi[q];
                be[q] = v; bi[q] = vi; v = tv; vi = ti;
            }
        }
    };

    for (int tile = 0; tile < 2; tile++) {
        __syncthreads();
        for (int i = threadIdx.x; i < 2048; i += 128) {
            int sp = tile * 2048 + i;
            float x = sb[sp*3+0], y = sb[sp*3+1], z = sb[sp*3+2];
            ss[i] = make_float4(x, y, z, fmaf(x,x, fmaf(y,y, z*z)));
        }
        __syncthreads();
        const int jb = tile * 2048;
#pragma unroll 1
        for (int j = 0; j < 2048; j += 4) {
            float4 q0 = ss[j+0];
            float4 q1 = ss[j+1];
            float4 q2 = ss[j+2];
            float4 q3 = ss[j+3];
            float e0 = fmaf(nx2,q0.x, fmaf(ny2,q0.y, fmaf(nz2,q0.z, q0.w)));
            float e1 = fmaf(nx2,q1.x, fmaf(ny2,q1.y, fmaf(nz2,q1.z, q1.w)));
            float e2 = fmaf(nx2,q2.x, fmaf(ny2,q2.y, fmaf(nz2,q2.z, q2.w)));
            float e3 = fmaf(nx2,q3.x, fmaf(ny2,q3.y, fmaf(nz2,q3.z, q3.w)));
            if (e0 < be[KK-1]) insert(e0, jb + j + 0);
            if (e1 < be[KK-1]) insert(e1, jb + j + 1);
            if (e2 < be[KK-1]) insert(e2, jb + j + 2);
            if (e3 < be[KK-1]) insert(e3, jb + j + 3);
        }
    }
#pragma unroll
    for (int q = 0; q < KK; q++) {
        g_d2 [row*KK+q] = fmaxf(be[q] + tt2, 0.f);
        g_idx[row*KK+q] = bi[q];
    }
}

// ---------------- build_ni + exact skip-dot store ------------------------
__global__ void __launch_bounds__(256) build_ni_kernel(
    const float* __restrict__ tmpl,
    const float* __restrict__ pfeat,
    float* __restrict__ out)
{
    __shared__ float sw [4][KK];
    __shared__ int   sid[4][KK];
    __shared__ float srow[4][KPAD1];
    __shared__ float swso[NREAL * 3];
    const int tid  = threadIdx.x;
    const int row0 = blockIdx.x * 4;

    for (int i = tid; i < NREAL * 3; i += 256) swso[i] = g_wso[i];

    if (tid < 32) {
        int rloc = tid >> 3, k = tid & 7;
        int row = row0 + rloc;
        sid[rloc][k] = g_idx[row*KK + k];
        float d = sqrtf(g_d2[row*KK + k]);
        float w = 1.f / (d + 1e-8f);
        float s = w;
#pragma unroll
        for (int o = 1; o < 8; o <<= 1)
            s += __shfl_xor_sync(0xffffffffu, s, o);
        sw[rloc][k] = w / s;
    }
    if (tid >= 32 && tid < 44) {
        int q = tid - 32; int rloc = q / 3, c = q % 3;
        srow[rloc][c] = tmpl[(row0 + rloc)*3 + c];
    }
    if (tid >= 64 && tid < 64 + 4*(KPAD1 - NREAL)) {
        int q = tid - 64; int rloc = q / (KPAD1 - NREAL), c = q % (KPAD1 - NREAL);
        srow[rloc][NREAL + c] = 0.f;
    }
    __syncthreads();

    {   // coalesced float4 gather, 64 threads per row
        const int rloc = tid >> 6, c4 = tid & 63;
        const int b = (row0 + rloc) >> 13;
        const float* pfb = pfeat + (size_t)b * SS * DD;
        float4 acc = make_float4(0.f, 0.f, 0.f, 0.f);
#pragma unroll
        for (int k = 0; k < KK; k++) {
            const float w = sw[rloc][k];
            const float4 v = *(const float4*)(pfb + (size_t)sid[rloc][k]*DD + c4*4);
            acc.x = fmaf(w, v.x, acc.x);
            acc.y = fmaf(w, v.y, acc.y);
            acc.z = fmaf(w, v.z, acc.z);
            acc.w = fmaf(w, v.w, acc.w);
        }
        srow[rloc][3 + c4*4 + 0] = acc.x;
        srow[rloc][3 + c4*4 + 1] = acc.y;
        srow[rloc][3 + c4*4 + 2] = acc.z;
        srow[rloc][3 + c4*4 + 3] = acc.w;
    }
    __syncthreads();

    // exact skip: warp w handles row rloc=w; STORE disp0 + 0.3*dot
    const int w = tid >> 5, lane = tid & 31;
    if (w < 4) {
        float d0 = 0.f, d1 = 0.f, d2 = 0.f;
        for (int c = lane; c < NREAL; c += 32) {
            const float v = srow[w][c];
            d0 = fmaf(v, swso[c*3+0], d0);
            d1 = fmaf(v, swso[c*3+1], d1);
            d2 = fmaf(v, swso[c*3+2], d2);
        }
#pragma unroll
        for (int o = 16; o > 0; o >>= 1) {
            d0 += __shfl_xor_sync(0xffffffffu, d0, o);
            d1 += __shfl_xor_sync(0xffffffffu, d1, o);
            d2 += __shfl_xor_sync(0xffffffffu, d2, o);
        }
        if (lane == 0) {
            const int row = row0 + w;
            const int bb  = row >> 13;
            out[row*3+0] = g_disp0[bb*3+0] + 0.3f * d0;
            out[row*3+1] = g_disp0[bb*3+1] + 0.3f * d1;
            out[row*3+2] = g_disp0[bb*3+2] + 0.3f * d2;
        }
    }

    // pack to bf16 hi/lo, 8B stores
    for (int p = tid; p < 4 * (KPAD1/4); p += 256) {
        int rloc = p / (KPAD1/4), q = p % (KPAD1/4);
        __nv_bfloat16 hv[4], lv[4];
#pragma unroll
        for (int s = 0; s < 4; s++)
            bf16split(srow[rloc][q*4 + s], hv[s], lv[s]);
        size_t base = (size_t)(row0 + rloc) * KPAD1 + q*4;
        *(uint2*)&g_ni_hi[base] = *(uint2*)hv;
        *(uint2*)&g_ni_lo[base] = *(uint2*)lv;
    }
}

// =============== mma.sync bf16 GEMM (128x64, BK=32) ======================
// MODE 0: GEMM1  A=ni hi/lo (K=288), B=w1t hi/lo (3-term comp) -> h1/m1
// MODE 1: GEMM2a A=h1 bf16 (K=256),  B=w2t hi (1-term) -> disp atomics
#define A_TILE_B 8192        // 128 rows x 64 bytes
#define B_TILE_B 4096        // 64 rows x 64 bytes

template<int MODE>
__global__ void __launch_bounds__(256, 3) mma_gemm(const float* __restrict__ biasext,
                                                   const float* __restrict__ Wo,
                                                   float* __restrict__ out)
{
    constexpr int  KTOT = (MODE == 0) ? KPAD1 : 256;
    constexpr int  NCH  = KTOT / 32;
    constexpr bool COMP = (MODE == 0);

    __shared__ __align__(128) __nv_bfloat16 sAhi[2][A_TILE_B/2];
    __shared__ __align__(128) __nv_bfloat16 sAlo[2][A_TILE_B/2];
    __shared__ __align__(128) __nv_bfloat16 sBhi[2][B_TILE_B/2];
    __shared__ __align__(128) __nv_bfloat16 sBlo[2][B_TILE_B/2];

    const int tid  = threadIdx.x;
    const int wid  = tid >> 5;
    const int lane = tid & 31;
    const int m0 = blockIdx.y * 128;
    const int n0 = blockIdx.x * 64;

    const __nv_bfloat16 *Ahi, *Alo, *Bhi, *Blo;
    const float* bias;
    if (MODE == 0) { Ahi = g_ni_hi; Alo = g_ni_lo; Bhi = g_w1t_hi; Blo = g_w1t_lo;
                     bias = g_bias_eff + (m0 >> 13) * NG1; }
    else           { Ahi = g_h1hi;  Alo = g_h1hi;  Bhi = g_w2t_hi; Blo = g_w2t_hi;
                     bias = biasext; }

    const uint32_t uAhi[2] = { smem_to_u32(sAhi[0]), smem_to_u32(sAhi[1]) };
    const uint32_t uAlo[2] = { smem_to_u32(sAlo[0]), smem_to_u32(sAlo[1]) };
    const uint32_t uBhi[2] = { smem_to_u32(sBhi[0]), smem_to_u32(sBhi[1]) };
    const uint32_t uBlo[2] = { smem_to_u32(sBlo[0]), smem_to_u32(sBlo[1]) };

    const int wm = (wid & 3) * 32;
    const int wn = (wid >> 2) * 32;

    float acc[2][4][4];
#pragma unroll
    for (int i = 0; i < 2; i++)
#pragma unroll
        for (int j = 0; j < 4; j++)
#pragma unroll
            for (int q = 0; q < 4; q++) acc[i][j][q] = 0.f;

    auto issue_stage = [&](int ch, int buf) {
        const int kc = ch * 32;
        constexpr int ACH   = COMP ? 1024 : 512;
        constexpr int NLOAD = COMP ? 6 : 3;
#pragma unroll
        for (int t = 0; t < NLOAD; t++) {
            int idx = tid + t * 256;
            if (idx < ACH) {
                int half  = COMP ? (idx >> 9) : 0;
                int sub   = idx & 511;
                int row   = sub >> 2;
                int chunk = sub & 3;
                const __nv_bfloat16* gp =
                    (half ? Alo : Ahi) + (size_t)(m0 + row) * KTOT + kc + chunk * 8;
                uint32_t off = swz64((uint32_t)(row * 64 + chunk * 16));
                CP_ASYNC16((half ? uAlo[buf] : uAhi[buf]) + off, gp);
            } else {
                int sub   = idx - ACH;
                int half  = COMP ? (sub >> 8) : 0;
                int s2    = sub & 255;
                int row   = s2 >> 2;
                int chunk = s2 & 3;
                const __nv_bfloat16* gp =
                    (half ? Blo : Bhi) + (size_t)(n0 + row) * KTOT + kc + chunk * 8;
                uint32_t off = swz64((uint32_t)(row * 64 + chunk * 16));
                CP_ASYNC16((half ? uBlo[buf] : uBhi[buf]) + off, gp);
            }
        }
        CP_COMMIT();
    };

    issue_stage(0, 0);
#pragma unroll 1
    for (int ch = 0; ch < NCH; ch++) {
        const int buf = ch & 1;
        if (ch + 1 < NCH) { issue_stage(ch + 1, buf ^ 1); CP_WAIT(1); }
        else              { CP_WAIT(0); }
        __syncthreads();

        const int lrow = (lane & 7) + ((lane >> 3) & 1) * 8;
        const int lk   = ((lane >> 4) & 1) * 8;
#pragma unroll
        for (int k16 = 0; k16 < 2; k16++) {
            const int kcol = k16 * 16 + lk;
            uint32_t bh[4][2], bl[4][2];
#pragma unroll
            for (int j2 = 0; j2 < 2; j2++) {
                uint32_t off = swz64((uint32_t)((wn + j2*16 + lrow) * 64 + kcol * 2));
                uint32_t r[4];
                ldsm4(r, uBhi[buf] + off);
                bh[j2*2][0] = r[0]; bh[j2*2+1][0] = r[1];
                bh[j2*2][1] = r[2]; bh[j2*2+1][1] = r[3];
                if (COMP) {
                    ldsm4(r, uBlo[buf] + off);
                    bl[j2*2][0] = r[0]; bl[j2*2+1][0] = r[1];
                    bl[j2*2][1] = r[2]; bl[j2*2+1][1] = r[3];
                }
            }
#pragma unroll
            for (int i = 0; i < 2; i++) {
                uint32_t af[4];
                uint32_t off = swz64((uint32_t)((wm + i*16 + lrow) * 64 + kcol * 2));
                ldsm4(af, uAhi[buf] + off);
#pragma unroll
                for (int j = 0; j < 4; j++) {
                    mma_bf16(acc[i][j], af, bh[j]);           // hi*hi
                    if (COMP) mma_bf16(acc[i][j], af, bl[j]); // hi*lo
                }
                if (COMP) {
                    ldsm4(af, uAlo[buf] + off);
#pragma unroll
                    for (int j = 0; j < 4; j++)
                        mma_bf16(acc[i][j], af, bh[j]);       // lo*hi
                }
            }
        }
        __syncthreads();
    }

    // ---- epilogue -------------------------------------------------------
    const int g     = lane >> 2;
    const int cpair = (lane & 3) * 2;
#pragma unroll
    for (int i = 0; i < 2; i++) {
#pragma unroll
        for (int half = 0; half < 2; half++) {
            const int r = m0 + wm + i*16 + g + half*8;
            if (MODE == 0) {
#pragma unroll
                for (int j = 0; j < 4; j++) {
                    const int c0 = n0 + wn + j*8 + cpair;
                    const float v0r = acc[i][j][half*2+0] + bias[c0];
                    const float v1r = acc[i][j][half*2+1] + bias[c0+1];
                    if (c0 < 256) {                 // h1: relu -> bf16
                        __nv_bfloat162 ph;
                        ph.x = __float2bfloat16(fmaxf(v0r, 0.f));
                        ph.y = __float2bfloat16(fmaxf(v1r, 0.f));
                        *(__nv_bfloat162*)&g_h1hi[(size_t)r*256 + c0] = ph;
                    } else {                        // m1: relu f32
                        float2 p; p.x = fmaxf(v0r, 0.f); p.y = fmaxf(v1r, 0.f);
                        *(float2*)&g_m1f[(size_t)r*128 + (c0-256)] = p;
                    }
                }
            } else {
                float d0 = 0.f, d1 = 0.f, d2 = 0.f;
#pragma unroll
                for (int j = 0; j < 4; j++) {
                    const int c0 = n0 + wn + j*8 + cpair;
                    float v0 = fmaxf(acc[i][j][half*2+0] + bias[c0],   0.f);
                    float v1 = fmaxf(acc[i][j][half*2+1] + bias[c0+1], 0.f);
                    d0 = fmaf(v0, Wo[c0*3+0], fmaf(v1, Wo[(c0+1)*3+0], d0));
                    d1 = fmaf(v0, Wo[c0*3+1], fmaf(v1, Wo[(c0+1)*3+1], d1));
                    d2 = fmaf(v0, Wo[c0*3+2], fmaf(v1, Wo[(c0+1)*3+2], d2));
                }
#pragma unroll
                for (int o = 1; o <= 2; o <<= 1) {
                    d0 += __shfl_xor_sync(0xffffffffu, d0, o);
                    d1 += __shfl_xor_sync(0xffffffffu, d1, o);
                    d2 += __shfl_xor_sync(0xffffffffu, d2, o);
                }
                if ((lane & 3) == 0) {
                    atomicAdd(&out[r*3+0], 0.3f * d0);
                    atomicAdd(&out[r*3+1], 0.3f * d1);
                    atomicAdd(&out[r*3+2], 0.3f * d2);
                }
            }
        }
    }
}

// ---------------- GEMM2b + mat head --------------------------------------
__global__ void gemm2b_kernel(const float* __restrict__ M2w,
                              const float* __restrict__ mb2,
                              const float* __restrict__ M3,
                              const float* __restrict__ mb3,
                              float* __restrict__ out)
{
    constexpr int BM=128, BN=64, BK=16, TM=8, TN=4, THREADS=256;
    __shared__ __align__(16) float As[BK*BM];
    __shared__ __align__(16) float Bs[BK*BN];
    const int tid  = threadIdx.x;
    const int row0 = blockIdx.x * BM;
    const int tm0  = (tid / (BN/TN)) * TM;
    const int tn0  = (tid % (BN/TN)) * TN;
    float4 pa[2], pb[1];

    auto loadg = [&](int k0) {
#pragma unroll
        for (int i = 0; i < 2; i++) {
            int idx = tid + i*THREADS; int m = idx / 4; int kv = idx % 4;
            pa[i] = *(const float4*)(g_m1f + (size_t)(row0+m)*128 + k0 + kv*4);
        }
        { int kr = tid / 16; int nv = tid % 16;
          pb[0] = *(const float4*)(M2w + (size_t)(k0 + kr)*64 + nv*4); }
    };
    auto stage = [&]() {
#pragma unroll
        for (int i = 0; i < 2; i++) {
            int idx = tid + i*THREADS; int m = idx / 4; int kv = idx % 4;
            As[(kv*4+0)*BM+m]=pa[i].x; As[(kv*4+1)*BM+m]=pa[i].y;
            As[(kv*4+2)*BM+m]=pa[i].z; As[(kv*4+3)*BM+m]=pa[i].w;
        }
        { int kr = tid / 16; int nv = tid % 16;
          *(float4*)&Bs[kr*BN + nv*4] = pb[0]; }
    };

    float acc[TM][TN];
#pragma unroll
    for (int i=0;i<TM;i++)
#pragma unroll
        for (int j=0;j<TN;j++) acc[i][j]=0.f;

    loadg(0);
#pragma unroll 1
    for (int t = 0; t < 128/BK; t++) {
        __syncthreads(); stage(); __syncthreads();
        if (t+1 < 128/BK) loadg((t+1)*BK);
#pragma unroll
        for (int kk = 0; kk < BK; kk++) {
            float af[TM], bf[TN];
#pragma unroll
            for (int i=0;i<TM/4;i++) *(float4*)&af[i*4] = *(const float4*)&As[kk*BM+tm0+i*4];
            *(float4*)&bf[0] = *(const float4*)&Bs[kk*BN+tn0];
#pragma unroll
            for (int i=0;i<TM;i++)
#pragma unroll
                for (int j=0;j<TN;j++) acc[i][j] = fmaf(af[i], bf[j], acc[i][j]);
        }
    }

    float mv[TM];
#pragma unroll
    for (int i=0;i<TM;i++) {
        float m = 0.f;
#pragma unroll
        for (int j=0;j<TN;j++) {
            int n = tn0 + j;
            m = fmaf(fmaxf(acc[i][j] + mb2[n], 0.f), M3[n], m);
        }
        mv[i] = m;
    }
#pragma unroll
    for (int o = 1; o <= 8; o <<= 1)
#pragma unroll
        for (int i=0;i<TM;i++)
            mv[i] += __shfl_xor_sync(0xffffffffu, mv[i], o);
    if ((tid & 15) == 0) {
        const float b3 = mb3[0];
#pragma unroll
        for (int i=0;i<TM;i++) {
            float x = mv[i] + b3;
            out[MATOFF + row0 + tm0 + i] = 1.f / (1.f + expf(-x));
        }
    }
}

// --------------------------------- launch --------------------------------
extern "C" void kernel_launch(void* const* d_in, const int* in_sizes, int n_in,
                              void* d_out, int out_size)
{
    const float* tmpl  = (const float*)d_in[0];
    const float* surf  = (const float*)d_in[1];
    const float* gfeat = (const float*)d_in[2];
    const float* pfeat = (const float*)d_in[3];
    const float* W1 = (const float*)d_in[4];
    const float* b1 = (const float*)d_in[5];
    const float* W2 = (const float*)d_in[6];
    const float* b2 = (const float*)d_in[7];
    const float* Ws = (const float*)d_in[8];
    const float* bs = (const float*)d_in[9];
    const float* Wo = (const float*)d_in[10];
    const float* bo = (const float*)d_in[11];
    const float* M1 = (const float*)d_in[12];
    const float* mb1 = (const float*)d_in[13];
    const float* M2 = (const float*)d_in[14];
    const float* mb2 = (const float*)d_in[15];
    const float* M3 = (const float*)d_in[16];
    const float* mb3 = (const float*)d_in[17];
    float* out = (float*)d_out;

    // 1-3: precompute (independent of KNN)
    prep1_kernel<<<17, 256>>>(Ws, Wo, W1, M1, b1, mb1, gfeat, bs, bo);
    w1pack_kernel<<<(NG1*KPAD1 + 255)/256, 256>>>(W1, M1);
    w2pack_kernel<<<256, 256>>>(W2);
    // 4: KNN (unchunked + ILP4)  <- profiled slot
    knn_kernel<<<dim3(TT/128, BB), 128>>>(tmpl, surf);
    // 5: ni build + skip-dot store
    build_ni_kernel<<<NIB, 256>>>(tmpl, pfeat, out);
    // 6: GEMM1  [32768 x 288] @ [288 x 384]
    mma_gemm<0><<<dim3(NG1/64, ROWS/128), 256>>>(nullptr, nullptr, nullptr);
    // 7: GEMM2a + disp head (atomic, 4x256 blocks)
    mma_gemm<1><<<dim3(256/64, ROWS/128), 256>>>(b2, Wo, out);
    // 8: GEMM2b + mat head
    gemm2b_kernel<<<ROWS/128, 256>>>(M2, mb2, M3, mb3, out);
}

// round 15
// speedup vs baseline: 1.1146x; 1.0714x over previous
#include <cuda_runtime.h>
#include <cuda_bf16.h>
#include <math.h>
#include <float.h>
#include <stdint.h>

// Problem constants
#define BB 4
#define TT 8192
#define SS 4096
#define DD 256
#define GG 512
#define KK 8
#define ROWS (BB*TT)        // 32768
#define NREAL 259           // template(3) + local(256); global folded into bias
#define KPAD1 288           // 9 * 32
#define NG1 384             // 256 (W1) + 128 (M1); skip branch folded out
#define MATOFF (ROWS*3)     // offset of mat in out
#define NIB (ROWS/4)        // 8192 ni blocks in build_ni

// ---------------- scratch (device globals; no allocation) ----------------
__device__ __align__(128) int   g_idx[ROWS * KK];
__device__ __align__(128) float g_d2 [ROWS * KK];
__device__ __align__(128) __nv_bfloat16 g_ni_hi[(size_t)ROWS * KPAD1];
__device__ __align__(128) __nv_bfloat16 g_ni_lo[(size_t)ROWS * KPAD1];
__device__ __align__(128) __nv_bfloat16 g_w1t_hi[NG1 * KPAD1];
__device__ __align__(128) __nv_bfloat16 g_w1t_lo[NG1 * KPAD1];
__device__ __align__(128) __nv_bfloat16 g_w2t_hi[256 * 256];
__device__ __align__(128) float g_bias_eff[BB * NG1];  // bias + gfeat@W_global
__device__ __align__(128) float g_wso[771 * 3];        // Ws @ Wo (fp32 exact)
__device__ __align__(128) float g_disp0[BB * 3];       // 0.3*(bo + (bs+gs).Wo)
__device__ __align__(128) __nv_bfloat16 g_h1hi[(size_t)ROWS * 256];
__device__ __align__(128) float g_m1f[(size_t)ROWS * 128];

// =================== helpers =============================================
__device__ __forceinline__ uint32_t smem_to_u32(const void* p) {
    uint32_t a;
    asm("{ .reg .u64 t; cvta.to.shared.u64 t, %1; cvt.u32.u64 %0, t; }" : "=r"(a) : "l"(p));
    return a;
}
__device__ __forceinline__ void ldsm4(uint32_t* r, uint32_t addr) {
    asm volatile("ldmatrix.sync.aligned.m8n8.x4.shared.b16 {%0,%1,%2,%3}, [%4];"
        : "=r"(r[0]), "=r"(r[1]), "=r"(r[2]), "=r"(r[3]) : "r"(addr));
}
__device__ __forceinline__ void mma_bf16(float* c, const uint32_t* a, const uint32_t* b) {
    asm volatile("mma.sync.aligned.m16n8k16.row.col.f32.bf16.bf16.f32 "
        "{%0,%1,%2,%3}, {%4,%5,%6,%7}, {%8,%9}, {%0,%1,%2,%3};"
        : "+f"(c[0]), "+f"(c[1]), "+f"(c[2]), "+f"(c[3])
        : "r"(a[0]), "r"(a[1]), "r"(a[2]), "r"(a[3]), "r"(b[0]), "r"(b[1]));
}
#define CP_ASYNC16(dst, src) \
    asm volatile("cp.async.cg.shared.global [%0], [%1], 16;" :: "r"(dst), "l"(src))
#define CP_COMMIT()  asm volatile("cp.async.commit_group;" ::: "memory")
#define CP_WAIT(n)   asm volatile("cp.async.wait_group %0;" :: "n"(n) : "memory")

__device__ __forceinline__ uint32_t swz64(uint32_t off) {
    return off ^ (((off >> 7) & 3u) << 4);
}
__device__ __forceinline__ void bf16split(float v, __nv_bfloat16& h, __nv_bfloat16& l) {
    h = __float2bfloat16(v);
    l = __float2bfloat16(v - __bfloat162float(h));
}

// ---------------- prep1: wso | bias_eff | disp0 (disjoint block ranges) --
__global__ void prep1_kernel(const float* __restrict__ Ws,
                             const float* __restrict__ Wo,
                             const float* __restrict__ W1,
                             const float* __restrict__ M1,
                             const float* __restrict__ b1,
                             const float* __restrict__ mb1,
                             const float* __restrict__ gfeat,
                             const float* __restrict__ bs,
                             const float* __restrict__ bo)
{
    const int bx = blockIdx.x, tid = threadIdx.x;
    if (bx < 10) {                        // wso = Ws @ Wo (771 x 3)
        int idx = bx * 256 + tid;
        if (idx < 771 * 3) {
            int k = idx / 3, o = idx % 3;
            float acc = 0.f;
#pragma unroll 8
            for (int h = 0; h < 256; h++)
                acc = fmaf(Ws[k*256 + h], Wo[h*3 + o], acc);
            g_wso[idx] = acc;
        }
    } else if (bx < 16) {                 // bias_eff (4 x 384)
        int idx = (bx - 10) * 256 + tid;
        if (idx < BB * NG1) {
            int b = idx / NG1, n = idx % NG1;
            const float* gf = gfeat + b * GG;
            float acc;
            if (n < 256) {
                acc = b1[n];
                const float* w = W1 + 259*256 + n;
#pragma unroll 8
                for (int j = 0; j < GG; j++) acc = fmaf(gf[j], w[j*256], acc);
            } else {
                acc = mb1[n-256];
                const float* w = M1 + 259*128 + (n - 256);
#pragma unroll 8
                for (int j = 0; j < GG; j++) acc = fmaf(gf[j], w[j*128], acc);
            }
            g_bias_eff[idx] = acc;
        }
    } else {                              // disp0
        __shared__ float sv[BB][256];
        const int h = tid;
#pragma unroll
        for (int b = 0; b < BB; b++) {
            float acc = bs[h];
            const float* gf = gfeat + b * GG;
#pragma unroll 8
            for (int j = 0; j < GG; j++)
                acc = fmaf(gf[j], Ws[(NREAL + j)*256 + h], acc);
            sv[b][h] = acc;
        }
        __syncthreads();
        if (tid < BB * 3) {
            int b = tid / 3, o = tid % 3;
            float acc = bo[o];
#pragma unroll 8
            for (int hh = 0; hh < 256; hh++)
                acc = fmaf(sv[b][hh], Wo[hh*3 + o], acc);
            g_disp0[tid] = 0.3f * acc;
        }
    }
}

// ---------------- w1pack: transpose+split W1/M1 to bf16 hi/lo ------------
__global__ void w1pack_kernel(const float* __restrict__ W1,
                              const float* __restrict__ M1)
{
    int idx = blockIdx.x * 256 + threadIdx.x;
    if (idx < NG1 * KPAD1) {
        int n = idx / KPAD1, k = idx % KPAD1;
        float v = 0.f;
        if (k < NREAL) {
            if (n < 256) v = W1[k*256 + n];
            else         v = M1[k*128 + (n-256)];
        }
        __nv_bfloat16 h, l; bf16split(v, h, l);
        g_w1t_hi[idx] = h; g_w1t_lo[idx] = l;
    }
}

// ---------------- w2pack: transpose W2 to bf16 ---------------------------
__global__ void w2pack_kernel(const float* __restrict__ W2)
{
    int idx = blockIdx.x * 256 + threadIdx.x;
    if (idx < 256 * 256) {
        int n = idx / 256, k = idx % 256;
        g_w2t_hi[idx] = __float2bfloat16(W2[k*256 + n]);
    }
}

// ---------------- KNN: 2-way surf split + ILP4 scan + merge --------------
// Block = 256 thr = 128 points x 2 chunks (c = tid>>7). Chunk-thread scans
// 2048 candidates (half of each 2048-tile). Key e = |s|^2 - 2 t.s.
// Merge of 2x8 exact fp32 keys preserves sequential tie semantics.
__global__ void __launch_bounds__(256) knn_kernel(
    const float* __restrict__ tmpl,
    const float* __restrict__ surf)
{
    __shared__ float4 ss[2048];          // 32 KB (xyz, |s|^2)
    __shared__ float  ce[16 * 128];      // 8 KB keys
    __shared__ int    ci[16 * 128];      // 8 KB indices
    const int tid = threadIdx.x;
    const int c   = tid >> 7;            // chunk 0/1
    const int p   = tid & 127;           // point-in-block
    const int b   = blockIdx.y;
    const int row = b * TT + blockIdx.x * 128 + p;

    const float tx = tmpl[row*3+0];
    const float ty = tmpl[row*3+1];
    const float tz = tmpl[row*3+2];
    const float nx2 = -2.f*tx, ny2 = -2.f*ty, nz2 = -2.f*tz;
    const float tt2 = fmaf(tx,tx, fmaf(ty,ty, tz*tz));

    float be[KK]; int bi[KK];
#pragma unroll
    for (int q = 0; q < KK; q++) { be[q] = FLT_MAX; bi[q] = 0; }
    const float* sb = surf + (size_t)b * SS * 3;

    auto insert = [&](float v, int vi) {
#pragma unroll
        for (int q = 0; q < KK; q++) {
            if (v < be[q]) {
                float tv = be[q]; int ti = bi[q];
                be[q] = v; bi[q] = vi; v = tv; vi = ti;
            }
        }
    };

    for (int tile = 0; tile < 2; tile++) {
        __syncthreads();
        for (int i = tid; i < 2048; i += 256) {
            int sp = tile * 2048 + i;
            float x = sb[sp*3+0], y = sb[sp*3+1], z = sb[sp*3+2];
            ss[i] = make_float4(x, y, z, fmaf(x,x, fmaf(y,y, z*z)));
        }
        __syncthreads();
        const int jb = tile * 2048;
        const int j0 = c * 1024;
#pragma unroll 1
        for (int j = j0; j < j0 + 1024; j += 4) {
            float4 q0 = ss[j+0];
            float4 q1 = ss[j+1];
            float4 q2 = ss[j+2];
            float4 q3 = ss[j+3];
            float e0 = fmaf(nx2,q0.x, fmaf(ny2,q0.y, fmaf(nz2,q0.z, q0.w)));
            float e1 = fmaf(nx2,q1.x, fmaf(ny2,q1.y, fmaf(nz2,q1.z, q1.w)));
            float e2 = fmaf(nx2,q2.x, fmaf(ny2,q2.y, fmaf(nz2,q2.z, q2.w)));
            float e3 = fmaf(nx2,q3.x, fmaf(ny2,q3.y, fmaf(nz2,q3.z, q3.w)));
            if (e0 < be[KK-1]) insert(e0, jb + j + 0);
            if (e1 < be[KK-1]) insert(e1, jb + j + 1);
            if (e2 < be[KK-1]) insert(e2, jb + j + 2);
            if (e3 < be[KK-1]) insert(e3, jb + j + 3);
        }
    }
    // publish per-chunk top-8 (stride-128: consecutive p -> consecutive bank)
#pragma unroll
    for (int q = 0; q < KK; q++) {
        ce[(c*KK + q)*128 + p] = be[q];
        ci[(c*KK + q)*128 + p] = bi[q];
    }
    __syncthreads();
    // merge 16 candidates per point; s order = chunk0 sorted, chunk1 sorted
    if (tid < 128) {
        float me[KK]; int mi[KK];
#pragma unroll
        for (int q = 0; q < KK; q++) { me[q] = FLT_MAX; mi[q] = 0; }
#pragma unroll
        for (int s = 0; s < 16; s++) {
            float v = ce[s*128 + tid];
            if (v < me[KK-1]) {
                int vi = ci[s*128 + tid];
#pragma unroll
                for (int q = 0; q < KK; q++) {
                    if (v < me[q]) {
                        float tv = me[q]; int ti = mi[q];
                        me[q] = v; mi[q] = vi;
                        v = tv; vi = ti;
                    }
                }
            }
        }
#pragma unroll
        for (int q = 0; q < KK; q++) {
            g_d2 [row*KK+q] = fmaxf(me[q] + tt2, 0.f);
            g_idx[row*KK+q] = mi[q];
        }
    }
}

// ---------------- build_ni + exact skip-dot store ------------------------
__global__ void __launch_bounds__(256) build_ni_kernel(
    const float* __restrict__ tmpl,
    const float* __restrict__ pfeat,
    float* __restrict__ out)
{
    __shared__ float sw [4][KK];
    __shared__ int   sid[4][KK];
    __shared__ float srow[4][KPAD1];
    __shared__ float swso[NREAL * 3];
    const int tid  = threadIdx.x;
    const int row0 = blockIdx.x * 4;

    for (int i = tid; i < NREAL * 3; i += 256) swso[i] = g_wso[i];

    if (tid < 32) {
        int rloc = tid >> 3, k = tid & 7;
        int row = row0 + rloc;
        sid[rloc][k] = g_idx[row*KK + k];
        float d = sqrtf(g_d2[row*KK + k]);
        float w = 1.f / (d + 1e-8f);
        float s = w;
#pragma unroll
        for (int o = 1; o < 8; o <<= 1)
            s += __shfl_xor_sync(0xffffffffu, s, o);
        sw[rloc][k] = w / s;
    }
    if (tid >= 32 && tid < 44) {
        int q = tid - 32; int rloc = q / 3, c = q % 3;
        srow[rloc][c] = tmpl[(row0 + rloc)*3 + c];
    }
    if (tid >= 64 && tid < 64 + 4*(KPAD1 - NREAL)) {
        int q = tid - 64; int rloc = q / (KPAD1 - NREAL), c = q % (KPAD1 - NREAL);
        srow[rloc][NREAL + c] = 0.f;
    }
    __syncthreads();

    {   // coalesced float4 gather, 64 threads per row
        const int rloc = tid >> 6, c4 = tid & 63;
        const int b = (row0 + rloc) >> 13;
        const float* pfb = pfeat + (size_t)b * SS * DD;
        float4 acc = make_float4(0.f, 0.f, 0.f, 0.f);
#pragma unroll
        for (int k = 0; k < KK; k++) {
            const float w = sw[rloc][k];
            const float4 v = *(const float4*)(pfb + (size_t)sid[rloc][k]*DD + c4*4);
            acc.x = fmaf(w, v.x, acc.x);
            acc.y = fmaf(w, v.y, acc.y);
            acc.z = fmaf(w, v.z, acc.z);
            acc.w = fmaf(w, v.w, acc.w);
        }
        srow[rloc][3 + c4*4 + 0] = acc.x;
        srow[rloc][3 + c4*4 + 1] = acc.y;
        srow[rloc][3 + c4*4 + 2] = acc.z;
        srow[rloc][3 + c4*4 + 3] = acc.w;
    }
    __syncthreads();

    // exact skip: warp w handles row rloc=w; STORE disp0 + 0.3*dot
    const int w = tid >> 5, lane = tid & 31;
    if (w < 4) {
        float d0 = 0.f, d1 = 0.f, d2 = 0.f;
        for (int c = lane; c < NREAL; c += 32) {
            const float v = srow[w][c];
            d0 = fmaf(v, swso[c*3+0], d0);
            d1 = fmaf(v, swso[c*3+1], d1);
            d2 = fmaf(v, swso[c*3+2], d2);
        }
#pragma unroll
        for (int o = 16; o > 0; o >>= 1) {
            d0 += __shfl_xor_sync(0xffffffffu, d0, o);
            d1 += __shfl_xor_sync(0xffffffffu, d1, o);
            d2 += __shfl_xor_sync(0xffffffffu, d2, o);
        }
        if (lane == 0) {
            const int row = row0 + w;
            const int bb  = row >> 13;
            out[row*3+0] = g_disp0[bb*3+0] + 0.3f * d0;
            out[row*3+1] = g_disp0[bb*3+1] + 0.3f * d1;
            out[row*3+2] = g_disp0[bb*3+2] + 0.3f * d2;
        }
    }

    // pack to bf16 hi/lo, 8B stores
    for (int p = tid; p < 4 * (KPAD1/4); p += 256) {
        int rloc = p / (KPAD1/4), q = p % (KPAD1/4);
        __nv_bfloat16 hv[4], lv[4];
#pragma unroll
        for (int s = 0; s < 4; s++)
            bf16split(srow[rloc][q*4 + s], hv[s], lv[s]);
        size_t base = (size_t)(row0 + rloc) * KPAD1 + q*4;
        *(uint2*)&g_ni_hi[base] = *(uint2*)hv;
        *(uint2*)&g_ni_lo[base] = *(uint2*)lv;
    }
}

// =============== mma.sync bf16 GEMM (128x64, BK=32) ======================
// MODE 0: GEMM1  A=ni hi/lo (K=288), B=w1t hi/lo (3-term comp) -> h1/m1
// MODE 1: GEMM2a A=h1 bf16 (K=256),  B=w2t hi (1-term) -> disp atomics
#define A_TILE_B 8192        // 128 rows x 64 bytes
#define B_TILE_B 4096        // 64 rows x 64 bytes

template<int MODE>
__global__ void __launch_bounds__(256, 3) mma_gemm(const float* __restrict__ biasext,
                                                   const float* __restrict__ Wo,
                                                   float* __restrict__ out)
{
    constexpr int  KTOT = (MODE == 0) ? KPAD1 : 256;
    constexpr int  NCH  = KTOT / 32;
    constexpr bool COMP = (MODE == 0);

    __shared__ __align__(128) __nv_bfloat16 sAhi[2][A_TILE_B/2];
    __shared__ __align__(128) __nv_bfloat16 sAlo[2][A_TILE_B/2];
    __shared__ __align__(128) __nv_bfloat16 sBhi[2][B_TILE_B/2];
    __shared__ __align__(128) __nv_bfloat16 sBlo[2][B_TILE_B/2];

    const int tid  = threadIdx.x;
    const int wid  = tid >> 5;
    const int lane = tid & 31;
    const int m0 = blockIdx.y * 128;
    const int n0 = blockIdx.x * 64;

    const __nv_bfloat16 *Ahi, *Alo, *Bhi, *Blo;
    const float* bias;
    if (MODE == 0) { Ahi = g_ni_hi; Alo = g_ni_lo; Bhi = g_w1t_hi; Blo = g_w1t_lo;
                     bias = g_bias_eff + (m0 >> 13) * NG1; }
    else           { Ahi = g_h1hi;  Alo = g_h1hi;  Bhi = g_w2t_hi; Blo = g_w2t_hi;
                     bias = biasext; }

    const uint32_t uAhi[2] = { smem_to_u32(sAhi[0]), smem_to_u32(sAhi[1]) };
    const uint32_t uAlo[2] = { smem_to_u32(sAlo[0]), smem_to_u32(sAlo[1]) };
    const uint32_t uBhi[2] = { smem_to_u32(sBhi[0]), smem_to_u32(sBhi[1]) };
    const uint32_t uBlo[2] = { smem_to_u32(sBlo[0]), smem_to_u32(sBlo[1]) };

    const int wm = (wid & 3) * 32;
    const int wn = (wid >> 2) * 32;

    float acc[2][4][4];
#pragma unroll
    for (int i = 0; i < 2; i++)
#pragma unroll
        for (int j = 0; j < 4; j++)
#pragma unroll
            for (int q = 0; q < 4; q++) acc[i][j][q] = 0.f;

    auto issue_stage = [&](int ch, int buf) {
        const int kc = ch * 32;
        constexpr int ACH   = COMP ? 1024 : 512;
        constexpr int NLOAD = COMP ? 6 : 3;
#pragma unroll
        for (int t = 0; t < NLOAD; t++) {
            int idx = tid + t * 256;
            if (idx < ACH) {
                int half  = COMP ? (idx >> 9) : 0;
                int sub   = idx & 511;
                int row   = sub >> 2;
                int chunk = sub & 3;
                const __nv_bfloat16* gp =
                    (half ? Alo : Ahi) + (size_t)(m0 + row) * KTOT + kc + chunk * 8;
                uint32_t off = swz64((uint32_t)(row * 64 + chunk * 16));
                CP_ASYNC16((half ? uAlo[buf] : uAhi[buf]) + off, gp);
            } else {
                int sub   = idx - ACH;
                int half  = COMP ? (sub >> 8) : 0;
                int s2    = sub & 255;
                int row   = s2 >> 2;
                int chunk = s2 & 3;
                const __nv_bfloat16* gp =
                    (half ? Blo : Bhi) + (size_t)(n0 + row) * KTOT + kc + chunk * 8;
                uint32_t off = swz64((uint32_t)(row * 64 + chunk * 16));
                CP_ASYNC16((half ? uBlo[buf] : uBhi[buf]) + off, gp);
            }
        }
        CP_COMMIT();
    };

    issue_stage(0, 0);
#pragma unroll 1
    for (int ch = 0; ch < NCH; ch++) {
        const int buf = ch & 1;
        if (ch + 1 < NCH) { issue_stage(ch + 1, buf ^ 1); CP_WAIT(1); }
        else              { CP_WAIT(0); }
        __syncthreads();

        const int lrow = (lane & 7) + ((lane >> 3) & 1) * 8;
        const int lk   = ((lane >> 4) & 1) * 8;
#pragma unroll
        for (int k16 = 0; k16 < 2; k16++) {
            const int kcol = k16 * 16 + lk;
            uint32_t bh[4][2], bl[4][2];
#pragma unroll
            for (int j2 = 0; j2 < 2; j2++) {
                uint32_t off = swz64((uint32_t)((wn + j2*16 + lrow) * 64 + kcol * 2));
                uint32_t r[4];
                ldsm4(r, uBhi[buf] + off);
                bh[j2*2][0] = r[0]; bh[j2*2+1][0] = r[1];
                bh[j2*2][1] = r[2]; bh[j2*2+1][1] = r[3];
                if (COMP) {
                    ldsm4(r, uBlo[buf] + off);
                    bl[j2*2][0] = r[0]; bl[j2*2+1][0] = r[1];
                    bl[j2*2][1] = r[2]; bl[j2*2+1][1] = r[3];
                }
            }
#pragma unroll
            for (int i = 0; i < 2; i++) {
                uint32_t af[4];
                uint32_t off = swz64((uint32_t)((wm + i*16 + lrow) * 64 + kcol * 2));
                ldsm4(af, uAhi[buf] + off);
#pragma unroll
                for (int j = 0; j < 4; j++) {
                    mma_bf16(acc[i][j], af, bh[j]);           // hi*hi
                    if (COMP) mma_bf16(acc[i][j], af, bl[j]); // hi*lo
                }
                if (COMP) {
                    ldsm4(af, uAlo[buf] + off);
#pragma unroll
                    for (int j = 0; j < 4; j++)
                        mma_bf16(acc[i][j], af, bh[j]);       // lo*hi
                }
            }
        }
        __syncthreads();
    }

    // ---- epilogue -------------------------------------------------------
    const int g     = lane >> 2;
    const int cpair = (lane & 3) * 2;
#pragma unroll
    for (int i = 0; i < 2; i++) {
#pragma unroll
        for (int half = 0; half < 2; half++) {
            const int r = m0 + wm + i*16 + g + half*8;
            if (MODE == 0) {
#pragma unroll
                for (int j = 0; j < 4; j++) {
                    const int c0 = n0 + wn + j*8 + cpair;
                    const float v0r = acc[i][j][half*2+0] + bias[c0];
                    const float v1r = acc[i][j][half*2+1] + bias[c0+1];
                    if (c0 < 256) {                 // h1: relu -> bf16
                        __nv_bfloat162 ph;
                        ph.x = __float2bfloat16(fmaxf(v0r, 0.f));
                        ph.y = __float2bfloat16(fmaxf(v1r, 0.f));
                        *(__nv_bfloat162*)&g_h1hi[(size_t)r*256 + c0] = ph;
                    } else {                        // m1: relu f32
                        float2 p; p.x = fmaxf(v0r, 0.f); p.y = fmaxf(v1r, 0.f);
                        *(float2*)&g_m1f[(size_t)r*128 + (c0-256)] = p;
                    }
                }
            } else {
                float d0 = 0.f, d1 = 0.f, d2 = 0.f;
#pragma unroll
                for (int j = 0; j < 4; j++) {
                    const int c0 = n0 + wn + j*8 + cpair;
                    float v0 = fmaxf(acc[i][j][half*2+0] + bias[c0],   0.f);
                    float v1 = fmaxf(acc[i][j][half*2+1] + bias[c0+1], 0.f);
                    d0 = fmaf(v0, Wo[c0*3+0], fmaf(v1, Wo[(c0+1)*3+0], d0));
                    d1 = fmaf(v0, Wo[c0*3+1], fmaf(v1, Wo[(c0+1)*3+1], d1));
                    d2 = fmaf(v0, Wo[c0*3+2], fmaf(v1, Wo[(c0+1)*3+2], d2));
                }
#pragma unroll
                for (int o = 1; o <= 2; o <<= 1) {
                    d0 += __shfl_xor_sync(0xffffffffu, d0, o);
                    d1 += __shfl_xor_sync(0xffffffffu, d1, o);
                    d2 += __shfl_xor_sync(0xffffffffu, d2, o);
                }
                if ((lane & 3) == 0) {
                    atomicAdd(&out[r*3+0], 0.3f * d0);
                    atomicAdd(&out[r*3+1], 0.3f * d1);
                    atomicAdd(&out[r*3+2], 0.3f * d2);
                }
            }
        }
    }
}

// ---------------- GEMM2b + mat head --------------------------------------
__global__ void gemm2b_kernel(const float* __restrict__ M2w,
                              const float* __restrict__ mb2,
                              const float* __restrict__ M3,
                              const float* __restrict__ mb3,
                              float* __restrict__ out)
{
    constexpr int BM=128, BN=64, BK=16, TM=8, TN=4, THREADS=256;
    __shared__ __align__(16) float As[BK*BM];
    __shared__ __align__(16) float Bs[BK*BN];
    const int tid  = threadIdx.x;
    const int row0 = blockIdx.x * BM;
    const int tm0  = (tid / (BN/TN)) * TM;
    const int tn0  = (tid % (BN/TN)) * TN;
    float4 pa[2], pb[1];

    auto loadg = [&](int k0) {
#pragma unroll
        for (int i = 0; i < 2; i++) {
            int idx = tid + i*THREADS; int m = idx / 4; int kv = idx % 4;
            pa[i] = *(const float4*)(g_m1f + (size_t)(row0+m)*128 + k0 + kv*4);
        }
        { int kr = tid / 16; int nv = tid % 16;
          pb[0] = *(const float4*)(M2w + (size_t)(k0 + kr)*64 + nv*4); }
    };
    auto stage = [&]() {
#pragma unroll
        for (int i = 0; i < 2; i++) {
            int idx = tid + i*THREADS; int m = idx / 4; int kv = idx % 4;
            As[(kv*4+0)*BM+m]=pa[i].x; As[(kv*4+1)*BM+m]=pa[i].y;
            As[(kv*4+2)*BM+m]=pa[i].z; As[(kv*4+3)*BM+m]=pa[i].w;
        }
        { int kr = tid / 16; int nv = tid % 16;
          *(float4*)&Bs[kr*BN + nv*4] = pb[0]; }
    };

    float acc[TM][TN];
#pragma unroll
    for (int i=0;i<TM;i++)
#pragma unroll
        for (int j=0;j<TN;j++) acc[i][j]=0.f;

    loadg(0);
#pragma unroll 1
    for (int t = 0; t < 128/BK; t++) {
        __syncthreads(); stage(); __syncthreads();
        if (t+1 < 128/BK) loadg((t+1)*BK);
#pragma unroll
        for (int kk = 0; kk < BK; kk++) {
            float af[TM], bf[TN];
#pragma unroll
            for (int i=0;i<TM/4;i++) *(float4*)&af[i*4] = *(const float4*)&As[kk*BM+tm0+i*4];
            *(float4*)&bf[0] = *(const float4*)&Bs[kk*BN+tn0];
#pragma unroll
            for (int i=0;i<TM;i++)
#pragma unroll
                for (int j=0;j<TN;j++) acc[i][j] = fmaf(af[i], bf[j], acc[i][j]);
        }
    }

    float mv[TM];
#pragma unroll
    for (int i=0;i<TM;i++) {
        float m = 0.f;
#pragma unroll
        for (int j=0;j<TN;j++) {
            int n = tn0 + j;
            m = fmaf(fmaxf(acc[i][j] + mb2[n], 0.f), M3[n], m);
        }
        mv[i] = m;
    }
#pragma unroll
    for (int o = 1; o <= 8; o <<= 1)
#pragma unroll
        for (int i=0;i<TM;i++)
            mv[i] += __shfl_xor_sync(0xffffffffu, mv[i], o);
    if ((tid & 15) == 0) {
        const float b3 = mb3[0];
#pragma unroll
        for (int i=0;i<TM;i++) {
            float x = mv[i] + b3;
            out[MATOFF + row0 + tm0 + i] = 1.f / (1.f + expf(-x));
        }
    }
}

// --------------------------------- launch --------------------------------
extern "C" void kernel_launch(void* const* d_in, const int* in_sizes, int n_in,
                              void* d_out, int out_size)
{
    const float* tmpl  = (const float*)d_in[0];
    const float* surf  = (const float*)d_in[1];
    const float* gfeat = (const float*)d_in[2];
    const float* pfeat = (const float*)d_in[3];
    const float* W1 = (const float*)d_in[4];
    const float* b1 = (const float*)d_in[5];
    const float* W2 = (const float*)d_in[6];
    const float* b2 = (const float*)d_in[7];
    const float* Ws = (const float*)d_in[8];
    const float* bs = (const float*)d_in[9];
    const float* Wo = (const float*)d_in[10];
    const float* bo = (const float*)d_in[11];
    const float* M1 = (const float*)d_in[12];
    const float* mb1 = (const float*)d_in[13];
    const float* M2 = (const float*)d_in[14];
    const float* mb2 = (const float*)d_in[15];
    const float* M3 = (const float*)d_in[16];
    const float* mb3 = (const float*)d_in[17];
    float* out = (float*)d_out;

    // 1-3: precompute (independent of KNN)
    prep1_kernel<<<17, 256>>>(Ws, Wo, W1, M1, b1, mb1, gfeat, bs, bo);
    w1pack_kernel<<<(NG1*KPAD1 + 255)/256, 256>>>(W1, M1);
    w2pack_kernel<<<256, 256>>>(W2);
    // 4: KNN (2-way split + ILP4)  <- profiled slot
    knn_kernel<<<dim3(TT/128, BB), 256>>>(tmpl, surf);
    // 5: ni build + skip-dot store
    build_ni_kernel<<<NIB, 256>>>(tmpl, pfeat, out);
    // 6: GEMM1  [32768 x 288] @ [288 x 384]
    mma_gemm<0><<<dim3(NG1/64, ROWS/128), 256>>>(nullptr, nullptr, nullptr);
    // 7: GEMM2a + disp head (atomic, 4x256 blocks)
    mma_gemm<1><<<dim3(256/64, ROWS/128), 256>>>(b2, Wo, out);
    // 8: GEMM2b + mat head
    gemm2b_kernel<<<ROWS/128, 256>>>(M2, mb2, M3, mb3, out);
}

// round 16
// speedup vs baseline: 1.1751x; 1.0543x over previous
#include <cuda_runtime.h>
#include <cuda_bf16.h>
#include <math.h>
#include <float.h>
#include <stdint.h>

// Problem constants
#define BB 4
#define TT 8192
#define SS 4096
#define DD 256
#define GG 512
#define KK 8
#define ROWS (BB*TT)        // 32768
#define NREAL 259           // template(3) + local(256); global folded into bias
#define KPAD1 288           // 9 * 32
#define NG1 384             // 256 (W1) + 128 (M1); skip branch folded out
#define MATOFF (ROWS*3)     // offset of mat in out
#define NIB (ROWS/4)        // 8192 ni blocks in build_ni

// fused front kernel block ranges
#define KNN_BLKS   256                       // (TT/128) * BB
#define PREP1_BLKS 17
#define W1P_BLKS   ((NG1*KPAD1)/256)         // 432
#define W2P_BLKS   256
#define FRONT_BLKS (KNN_BLKS + PREP1_BLKS + W1P_BLKS + W2P_BLKS)  // 961

// ---------------- scratch (device globals; no allocation) ----------------
__device__ __align__(128) int   g_idx[ROWS * KK];
__device__ __align__(128) float g_d2 [ROWS * KK];
__device__ __align__(128) __nv_bfloat16 g_ni_hi[(size_t)ROWS * KPAD1];
__device__ __align__(128) __nv_bfloat16 g_ni_lo[(size_t)ROWS * KPAD1];
__device__ __align__(128) __nv_bfloat16 g_w1t_hi[NG1 * KPAD1];
__device__ __align__(128) __nv_bfloat16 g_w1t_lo[NG1 * KPAD1];
__device__ __align__(128) __nv_bfloat16 g_w2t_hi[256 * 256];
__device__ __align__(128) float g_bias_eff[BB * NG1];  // bias + gfeat@W_global
__device__ __align__(128) float g_wso[771 * 3];        // Ws @ Wo (fp32 exact)
__device__ __align__(128) float g_disp0[BB * 3];       // 0.3*(bo + (bs+gs).Wo)
__device__ __align__(128) __nv_bfloat16 g_h1hi[(size_t)ROWS * 256];
__device__ __align__(128) float g_m1f[(size_t)ROWS * 128];

// =================== helpers =============================================
__device__ __forceinline__ uint32_t smem_to_u32(const void* p) {
    uint32_t a;
    asm("{ .reg .u64 t; cvta.to.shared.u64 t, %1; cvt.u32.u64 %0, t; }" : "=r"(a) : "l"(p));
    return a;
}
__device__ __forceinline__ void ldsm4(uint32_t* r, uint32_t addr) {
    asm volatile("ldmatrix.sync.aligned.m8n8.x4.shared.b16 {%0,%1,%2,%3}, [%4];"
        : "=r"(r[0]), "=r"(r[1]), "=r"(r[2]), "=r"(r[3]) : "r"(addr));
}
__device__ __forceinline__ void mma_bf16(float* c, const uint32_t* a, const uint32_t* b) {
    asm volatile("mma.sync.aligned.m16n8k16.row.col.f32.bf16.bf16.f32 "
        "{%0,%1,%2,%3}, {%4,%5,%6,%7}, {%8,%9}, {%0,%1,%2,%3};"
        : "+f"(c[0]), "+f"(c[1]), "+f"(c[2]), "+f"(c[3])
        : "r"(a[0]), "r"(a[1]), "r"(a[2]), "r"(a[3]), "r"(b[0]), "r"(b[1]));
}
#define CP_ASYNC16(dst, src) \
    asm volatile("cp.async.cg.shared.global [%0], [%1], 16;" :: "r"(dst), "l"(src))
#define CP_COMMIT()  asm volatile("cp.async.commit_group;" ::: "memory")
#define CP_WAIT(n)   asm volatile("cp.async.wait_group %0;" :: "n"(n) : "memory")

__device__ __forceinline__ uint32_t swz64(uint32_t off) {
    return off ^ (((off >> 7) & 3u) << 4);
}
__device__ __forceinline__ void bf16split(float v, __nv_bfloat16& h, __nv_bfloat16& l) {
    h = __float2bfloat16(v);
    l = __float2bfloat16(v - __bfloat162float(h));
}

// ======== fused front: KNN (2-way split + ILP4) | prep1 | w1pack | w2pack
__global__ void __launch_bounds__(256) front_kernel(
    const float* __restrict__ tmpl,
    const float* __restrict__ surf,
    const float* __restrict__ Ws,
    const float* __restrict__ Wo,
    const float* __restrict__ W1,
    const float* __restrict__ M1,
    const float* __restrict__ b1,
    const float* __restrict__ mb1,
    const float* __restrict__ gfeat,
    const float* __restrict__ bs,
    const float* __restrict__ bo,
    const float* __restrict__ W2)
{
    __shared__ float4 ss[2048];          // 32 KB (xyz, |s|^2)
    __shared__ float  ce[16 * 128];      // 8 KB keys   (prep1 aliases this)
    __shared__ int    ci[16 * 128];      // 8 KB indices
    const int bid = blockIdx.x;
    const int tid = threadIdx.x;

    if (bid >= KNN_BLKS) {
        const int pb = bid - KNN_BLKS;
        if (pb < PREP1_BLKS) {
            // ---- prep1: wso | bias_eff | disp0 --------------------------
            const int bx = pb;
            if (bx < 10) {                        // wso = Ws @ Wo (771 x 3)
                int idx = bx * 256 + tid;
                if (idx < 771 * 3) {
                    int k = idx / 3, o = idx % 3;
                    float acc = 0.f;
#pragma unroll 8
                    for (int h = 0; h < 256; h++)
                        acc = fmaf(Ws[k*256 + h], Wo[h*3 + o], acc);
                    g_wso[idx] = acc;
                }
            } else if (bx < 16) {                 // bias_eff (4 x 384)
                int idx = (bx - 10) * 256 + tid;
                if (idx < BB * NG1) {
                    int b = idx / NG1, n = idx % NG1;
                    const float* gf = gfeat + b * GG;
                    float acc;
                    if (n < 256) {
                        acc = b1[n];
                        const float* w = W1 + 259*256 + n;
#pragma unroll 8
                        for (int j = 0; j < GG; j++) acc = fmaf(gf[j], w[j*256], acc);
                    } else {
                        acc = mb1[n-256];
                        const float* w = M1 + 259*128 + (n - 256);
#pragma unroll 8
                        for (int j = 0; j < GG; j++) acc = fmaf(gf[j], w[j*128], acc);
                    }
                    g_bias_eff[idx] = acc;
                }
            } else {                              // disp0 (alias ce as sv)
                float* sv = ce;                   // [BB][256] = 4 KB
                const int h = tid;
#pragma unroll
                for (int b = 0; b < BB; b++) {
                    float acc = bs[h];
                    const float* gf = gfeat + b * GG;
#pragma unroll 8
                    for (int j = 0; j < GG; j++)
                        acc = fmaf(gf[j], Ws[(NREAL + j)*256 + h], acc);
                    sv[b*256 + h] = acc;
                }
                __syncthreads();
                if (tid < BB * 3) {
                    int b = tid / 3, o = tid % 3;
                    float acc = bo[o];
#pragma unroll 8
                    for (int hh = 0; hh < 256; hh++)
                        acc = fmaf(sv[b*256 + hh], Wo[hh*3 + o], acc);
                    g_disp0[tid] = 0.3f * acc;
                }
            }
        } else if (pb < PREP1_BLKS + W1P_BLKS) {
            // ---- w1pack -------------------------------------------------
            int idx = (pb - PREP1_BLKS) * 256 + tid;
            if (idx < NG1 * KPAD1) {
                int n = idx / KPAD1, k = idx % KPAD1;
                float v = 0.f;
                if (k < NREAL) {
                    if (n < 256) v = W1[k*256 + n];
                    else         v = M1[k*128 + (n-256)];
                }
                __nv_bfloat16 h, l; bf16split(v, h, l);
                g_w1t_hi[idx] = h; g_w1t_lo[idx] = l;
            }
        } else {
            // ---- w2pack -------------------------------------------------
            int idx = (pb - PREP1_BLKS - W1P_BLKS) * 256 + tid;
            if (idx < 256 * 256) {
                int n = idx / 256, k = idx % 256;
                g_w2t_hi[idx] = __float2bfloat16(W2[k*256 + n]);
            }
        }
        return;
    }

    // ---- KNN path (identical to R15) ------------------------------------
    const int c   = tid >> 7;            // chunk 0/1
    const int p   = tid & 127;           // point-in-block
    const int b   = bid >> 6;            // bid / (TT/128)
    const int bx  = bid & 63;
    const int row = b * TT + bx * 128 + p;

    const float tx = tmpl[row*3+0];
    const float ty = tmpl[row*3+1];
    const float tz = tmpl[row*3+2];
    const float nx2 = -2.f*tx, ny2 = -2.f*ty, nz2 = -2.f*tz;
    const float tt2 = fmaf(tx,tx, fmaf(ty,ty, tz*tz));

    float be[KK]; int bi[KK];
#pragma unroll
    for (int q = 0; q < KK; q++) { be[q] = FLT_MAX; bi[q] = 0; }
    const float* sb = surf + (size_t)b * SS * 3;

    auto insert = [&](float v, int vi) {
#pragma unroll
        for (int q = 0; q < KK; q++) {
            if (v < be[q]) {
                float tv = be[q]; int ti = bi[q];
                be[q] = v; bi[q] = vi; v = tv; vi = ti;
            }
        }
    };

    for (int tile = 0; tile < 2; tile++) {
        __syncthreads();
        for (int i = tid; i < 2048; i += 256) {
            int sp = tile * 2048 + i;
            float x = sb[sp*3+0], y = sb[sp*3+1], z = sb[sp*3+2];
            ss[i] = make_float4(x, y, z, fmaf(x,x, fmaf(y,y, z*z)));
        }
        __syncthreads();
        const int jb = tile * 2048;
        const int j0 = c * 1024;
#pragma unroll 1
        for (int j = j0; j < j0 + 1024; j += 4) {
            float4 q0 = ss[j+0];
            float4 q1 = ss[j+1];
            float4 q2 = ss[j+2];
            float4 q3 = ss[j+3];
            float e0 = fmaf(nx2,q0.x, fmaf(ny2,q0.y, fmaf(nz2,q0.z, q0.w)));
            float e1 = fmaf(nx2,q1.x, fmaf(ny2,q1.y, fmaf(nz2,q1.z, q1.w)));
            float e2 = fmaf(nx2,q2.x, fmaf(ny2,q2.y, fmaf(nz2,q2.z, q2.w)));
            float e3 = fmaf(nx2,q3.x, fmaf(ny2,q3.y, fmaf(nz2,q3.z, q3.w)));
            if (e0 < be[KK-1]) insert(e0, jb + j + 0);
            if (e1 < be[KK-1]) insert(e1, jb + j + 1);
            if (e2 < be[KK-1]) insert(e2, jb + j + 2);
            if (e3 < be[KK-1]) insert(e3, jb + j + 3);
        }
    }
#pragma unroll
    for (int q = 0; q < KK; q++) {
        ce[(c*KK + q)*128 + p] = be[q];
        ci[(c*KK + q)*128 + p] = bi[q];
    }
    __syncthreads();
    if (tid < 128) {
        float me[KK]; int mi[KK];
#pragma unroll
        for (int q = 0; q < KK; q++) { me[q] = FLT_MAX; mi[q] = 0; }
#pragma unroll
        for (int s = 0; s < 16; s++) {
            float v = ce[s*128 + tid];
            if (v < me[KK-1]) {
                int vi = ci[s*128 + tid];
#pragma unroll
                for (int q = 0; q < KK; q++) {
                    if (v < me[q]) {
                        float tv = me[q]; int ti = mi[q];
                        me[q] = v; mi[q] = vi;
                        v = tv; vi = ti;
                    }
                }
            }
        }
#pragma unroll
        for (int q = 0; q < KK; q++) {
            g_d2 [row*KK+q] = fmaxf(me[q] + tt2, 0.f);
            g_idx[row*KK+q] = mi[q];
        }
    }
}

// ---------------- build_ni + exact skip-dot store ------------------------
__global__ void __launch_bounds__(256) build_ni_kernel(
    const float* __restrict__ tmpl,
    const float* __restrict__ pfeat,
    float* __restrict__ out)
{
    __shared__ float sw [4][KK];
    __shared__ int   sid[4][KK];
    __shared__ float srow[4][KPAD1];
    __shared__ float swso[NREAL * 3];
    const int tid  = threadIdx.x;
    const int row0 = blockIdx.x * 4;

    for (int i = tid; i < NREAL * 3; i += 256) swso[i] = g_wso[i];

    if (tid < 32) {
        int rloc = tid >> 3, k = tid & 7;
        int row = row0 + rloc;
        sid[rloc][k] = g_idx[row*KK + k];
        float d = sqrtf(g_d2[row*KK + k]);
        float w = 1.f / (d + 1e-8f);
        float s = w;
#pragma unroll
        for (int o = 1; o < 8; o <<= 1)
            s += __shfl_xor_sync(0xffffffffu, s, o);
        sw[rloc][k] = w / s;
    }
    if (tid >= 32 && tid < 44) {
        int q = tid - 32; int rloc = q / 3, c = q % 3;
        srow[rloc][c] = tmpl[(row0 + rloc)*3 + c];
    }
    if (tid >= 64 && tid < 64 + 4*(KPAD1 - NREAL)) {
        int q = tid - 64; int rloc = q / (KPAD1 - NREAL), c = q % (KPAD1 - NREAL);
        srow[rloc][NREAL + c] = 0.f;
    }
    __syncthreads();

    {   // coalesced float4 gather, 64 threads per row
        const int rloc = tid >> 6, c4 = tid & 63;
        const int b = (row0 + rloc) >> 13;
        const float* pfb = pfeat + (size_t)b * SS * DD;
        float4 acc = make_float4(0.f, 0.f, 0.f, 0.f);
#pragma unroll
        for (int k = 0; k < KK; k++) {
            const float w = sw[rloc][k];
            const float4 v = *(const float4*)(pfb + (size_t)sid[rloc][k]*DD + c4*4);
            acc.x = fmaf(w, v.x, acc.x);
            acc.y = fmaf(w, v.y, acc.y);
            acc.z = fmaf(w, v.z, acc.z);
            acc.w = fmaf(w, v.w, acc.w);
        }
        srow[rloc][3 + c4*4 + 0] = acc.x;
        srow[rloc][3 + c4*4 + 1] = acc.y;
        srow[rloc][3 + c4*4 + 2] = acc.z;
        srow[rloc][3 + c4*4 + 3] = acc.w;
    }
    __syncthreads();

    // exact skip: warp w handles row rloc=w; STORE disp0 + 0.3*dot
    const int w = tid >> 5, lane = tid & 31;
    if (w < 4) {
        float d0 = 0.f, d1 = 0.f, d2 = 0.f;
        for (int c = lane; c < NREAL; c += 32) {
            const float v = srow[w][c];
            d0 = fmaf(v, swso[c*3+0], d0);
            d1 = fmaf(v, swso[c*3+1], d1);
            d2 = fmaf(v, swso[c*3+2], d2);
        }
#pragma unroll
        for (int o = 16; o > 0; o >>= 1) {
            d0 += __shfl_xor_sync(0xffffffffu, d0, o);
            d1 += __shfl_xor_sync(0xffffffffu, d1, o);
            d2 += __shfl_xor_sync(0xffffffffu, d2, o);
        }
        if (lane == 0) {
            const int row = row0 + w;
            const int bb  = row >> 13;
            out[row*3+0] = g_disp0[bb*3+0] + 0.3f * d0;
            out[row*3+1] = g_disp0[bb*3+1] + 0.3f * d1;
            out[row*3+2] = g_disp0[bb*3+2] + 0.3f * d2;
        }
    }

    // pack to bf16 hi/lo, 8B stores
    for (int p = tid; p < 4 * (KPAD1/4); p += 256) {
        int rloc = p / (KPAD1/4), q = p % (KPAD1/4);
        __nv_bfloat16 hv[4], lv[4];
#pragma unroll
        for (int s = 0; s < 4; s++)
            bf16split(srow[rloc][q*4 + s], hv[s], lv[s]);
        size_t base = (size_t)(row0 + rloc) * KPAD1 + q*4;
        *(uint2*)&g_ni_hi[base] = *(uint2*)hv;
        *(uint2*)&g_ni_lo[base] = *(uint2*)lv;
    }
}

// =============== mma.sync bf16 GEMM (128x64, BK=32) ======================
// MODE 0: GEMM1  A=ni hi/lo (K=288), B=w1t hi/lo (3-term comp) -> h1/m1
// MODE 1: grid (5, 256): x<4 GEMM2a (A=h1, B=w2t, 1-term, disp atomics);
//         x==4 gemm2b path (SIMT fp32, mat head), smem aliased into sAhi.
#define A_TILE_B 8192        // 128 rows x 64 bytes
#define B_TILE_B 4096        // 64 rows x 64 bytes

template<int MODE>
__global__ void __launch_bounds__(256, 3) mma_gemm(const float* __restrict__ biasext,
                                                   const float* __restrict__ Wo,
                                                   float* __restrict__ out,
                                                   const float* __restrict__ M2w,
                                                   const float* __restrict__ mb2,
                                                   const float* __restrict__ M3,
                                                   const float* __restrict__ mb3)
{
    constexpr int  KTOT = (MODE == 0) ? KPAD1 : 256;
    constexpr int  NCH  = KTOT / 32;
    constexpr bool COMP = (MODE == 0);

    __shared__ __align__(128) __nv_bfloat16 sAhi[2][A_TILE_B/2];
    __shared__ __align__(128) __nv_bfloat16 sAlo[2][A_TILE_B/2];
    __shared__ __align__(128) __nv_bfloat16 sBhi[2][B_TILE_B/2];
    __shared__ __align__(128) __nv_bfloat16 sBlo[2][B_TILE_B/2];

    const int tid  = threadIdx.x;

    if (MODE == 1 && blockIdx.x == 4) {
        // ---------- gemm2b + mat head (smem aliased) ---------------------
        constexpr int BM=128, BN=64, BK=16, TM=8, TN=4, THREADS=256;
        float* As = (float*)&sAhi[0][0];   // 8 KB
        float* Bs = (float*)&sAhi[1][0];   // 4 KB used
        const int row0 = blockIdx.y * BM;
        const int tm0  = (tid / (BN/TN)) * TM;
        const int tn0  = (tid % (BN/TN)) * TN;
        float4 pa[2], pb[1];

        auto loadg = [&](int k0) {
#pragma unroll
            for (int i = 0; i < 2; i++) {
                int idx = tid + i*THREADS; int m = idx / 4; int kv = idx % 4;
                pa[i] = *(const float4*)(g_m1f + (size_t)(row0+m)*128 + k0 + kv*4);
            }
            { int kr = tid / 16; int nv = tid % 16;
              pb[0] = *(const float4*)(M2w + (size_t)(k0 + kr)*64 + nv*4); }
        };
        auto stage = [&]() {
#pragma unroll
            for (int i = 0; i < 2; i++) {
                int idx = tid + i*THREADS; int m = idx / 4; int kv = idx % 4;
                As[(kv*4+0)*BM+m]=pa[i].x; As[(kv*4+1)*BM+m]=pa[i].y;
                As[(kv*4+2)*BM+m]=pa[i].z; As[(kv*4+3)*BM+m]=pa[i].w;
            }
            { int kr = tid / 16; int nv = tid % 16;
              *(float4*)&Bs[kr*BN + nv*4] = pb[0]; }
        };

        float acc[TM][TN];
#pragma unroll
        for (int i=0;i<TM;i++)
#pragma unroll
            for (int j=0;j<TN;j++) acc[i][j]=0.f;

        loadg(0);
#pragma unroll 1
        for (int t = 0; t < 128/BK; t++) {
            __syncthreads(); stage(); __syncthreads();
            if (t+1 < 128/BK) loadg((t+1)*BK);
#pragma unroll
            for (int kk = 0; kk < BK; kk++) {
                float af[TM], bf[TN];
#pragma unroll
                for (int i=0;i<TM/4;i++) *(float4*)&af[i*4] = *(const float4*)&As[kk*BM+tm0+i*4];
                *(float4*)&bf[0] = *(const float4*)&Bs[kk*BN+tn0];
#pragma unroll
                for (int i=0;i<TM;i++)
#pragma unroll
                    for (int j=0;j<TN;j++) acc[i][j] = fmaf(af[i], bf[j], acc[i][j]);
            }
        }

        float mv[TM];
#pragma unroll
        for (int i=0;i<TM;i++) {
            float m = 0.f;
#pragma unroll
            for (int j=0;j<TN;j++) {
                int n = tn0 + j;
                m = fmaf(fmaxf(acc[i][j] + mb2[n], 0.f), M3[n], m);
            }
            mv[i] = m;
        }
#pragma unroll
        for (int o = 1; o <= 8; o <<= 1)
#pragma unroll
            for (int i=0;i<TM;i++)
                mv[i] += __shfl_xor_sync(0xffffffffu, mv[i], o);
        if ((tid & 15) == 0) {
            const float b3 = mb3[0];
#pragma unroll
            for (int i=0;i<TM;i++) {
                float x = mv[i] + b3;
                out[MATOFF + row0 + tm0 + i] = 1.f / (1.f + expf(-x));
            }
        }
        return;
    }

    // ---------- tensor GEMM paths ----------------------------------------
    const int wid  = tid >> 5;
    const int lane = tid & 31;
    const int m0 = blockIdx.y * 128;
    const int n0 = blockIdx.x * 64;

    const __nv_bfloat16 *Ahi, *Alo, *Bhi, *Blo;
    const float* bias;
    if (MODE == 0) { Ahi = g_ni_hi; Alo = g_ni_lo; Bhi = g_w1t_hi; Blo = g_w1t_lo;
                     bias = g_bias_eff + (m0 >> 13) * NG1; }
    else           { Ahi = g_h1hi;  Alo = g_h1hi;  Bhi = g_w2t_hi; Blo = g_w2t_hi;
                     bias = biasext; }

    const uint32_t uAhi[2] = { smem_to_u32(sAhi[0]), smem_to_u32(sAhi[1]) };
    const uint32_t uAlo[2] = { smem_to_u32(sAlo[0]), smem_to_u32(sAlo[1]) };
    const uint32_t uBhi[2] = { smem_to_u32(sBhi[0]), smem_to_u32(sBhi[1]) };
    const uint32_t uBlo[2] = { smem_to_u32(sBlo[0]), smem_to_u32(sBlo[1]) };

    const int wm = (wid & 3) * 32;
    const int wn = (wid >> 2) * 32;

    float acc[2][4][4];
#pragma unroll
    for (int i = 0; i < 2; i++)
#pragma unroll
        for (int j = 0; j < 4; j++)
#pragma unroll
            for (int q = 0; q < 4; q++) acc[i][j][q] = 0.f;

    auto issue_stage = [&](int ch, int buf) {
        const int kc = ch * 32;
        constexpr int ACH   = COMP ? 1024 : 512;
        constexpr int NLOAD = COMP ? 6 : 3;
#pragma unroll
        for (int t = 0; t < NLOAD; t++) {
            int idx = tid + t * 256;
            if (idx < ACH) {
                int half  = COMP ? (idx >> 9) : 0;
                int sub   = idx & 511;
                int row   = sub >> 2;
                int chunk = sub & 3;
                const __nv_bfloat16* gp =
                    (half ? Alo : Ahi) + (size_t)(m0 + row) * KTOT + kc + chunk * 8;
                uint32_t off = swz64((uint32_t)(row * 64 + chunk * 16));
                CP_ASYNC16((half ? uAlo[buf] : uAhi[buf]) + off, gp);
            } else {
                int sub   = idx - ACH;
                int half  = COMP ? (sub >> 8) : 0;
                int s2    = sub & 255;
                int row   = s2 >> 2;
                int chunk = s2 & 3;
                const __nv_bfloat16* gp =
                    (half ? Blo : Bhi) + (size_t)(n0 + row) * KTOT + kc + chunk * 8;
                uint32_t off = swz64((uint32_t)(row * 64 + chunk * 16));
                CP_ASYNC16((half ? uBlo[buf] : uBhi[buf]) + off, gp);
            }
        }
        CP_COMMIT();
    };

    issue_stage(0, 0);
#pragma unroll 1
    for (int ch = 0; ch < NCH; ch++) {
        const int buf = ch & 1;
        if (ch + 1 < NCH) { issue_stage(ch + 1, buf ^ 1); CP_WAIT(1); }
        else              { CP_WAIT(0); }
        __syncthreads();

        const int lrow = (lane & 7) + ((lane >> 3) & 1) * 8;
        const int lk   = ((lane >> 4) & 1) * 8;
#pragma unroll
        for (int k16 = 0; k16 < 2; k16++) {
            const int kcol = k16 * 16 + lk;
            uint32_t bh[4][2], bl[4][2];
#pragma unroll
            for (int j2 = 0; j2 < 2; j2++) {
                uint32_t off = swz64((uint32_t)((wn + j2*16 + lrow) * 64 + kcol * 2));
                uint32_t r[4];
                ldsm4(r, uBhi[buf] + off);
                bh[j2*2][0] = r[0]; bh[j2*2+1][0] = r[1];
                bh[j2*2][1] = r[2]; bh[j2*2+1][1] = r[3];
                if (COMP) {
                    ldsm4(r, uBlo[buf] + off);
                    bl[j2*2][0] = r[0]; bl[j2*2+1][0] = r[1];
                    bl[j2*2][1] = r[2]; bl[j2*2+1][1] = r[3];
                }
            }
#pragma unroll
            for (int i = 0; i < 2; i++) {
                uint32_t af[4];
                uint32_t off = swz64((uint32_t)((wm + i*16 + lrow) * 64 + kcol * 2));
                ldsm4(af, uAhi[buf] + off);
#pragma unroll
                for (int j = 0; j < 4; j++) {
                    mma_bf16(acc[i][j], af, bh[j]);           // hi*hi
                    if (COMP) mma_bf16(acc[i][j], af, bl[j]); // hi*lo
                }
                if (COMP) {
                    ldsm4(af, uAlo[buf] + off);
#pragma unroll
                    for (int j = 0; j < 4; j++)
                        mma_bf16(acc[i][j], af, bh[j]);       // lo*hi
                }
            }
        }
        __syncthreads();
    }

    // ---- epilogue -------------------------------------------------------
    const int g     = lane >> 2;
    const int cpair = (lane & 3) * 2;
#pragma unroll
    for (int i = 0; i < 2; i++) {
#pragma unroll
        for (int half = 0; half < 2; half++) {
            const int r = m0 + wm + i*16 + g + half*8;
            if (MODE == 0) {
#pragma unroll
                for (int j = 0; j < 4; j++) {
                    const int c0 = n0 + wn + j*8 + cpair;
                    const float v0r = acc[i][j][half*2+0] + bias[c0];
                    const float v1r = acc[i][j][half*2+1] + bias[c0+1];
                    if (c0 < 256) {                 // h1: relu -> bf16
                        __nv_bfloat162 ph;
                        ph.x = __float2bfloat16(fmaxf(v0r, 0.f));
                        ph.y = __float2bfloat16(fmaxf(v1r, 0.f));
                        *(__nv_bfloat162*)&g_h1hi[(size_t)r*256 + c0] = ph;
                    } else {                        // m1: relu f32
                        float2 p; p.x = fmaxf(v0r, 0.f); p.y = fmaxf(v1r, 0.f);
                        *(float2*)&g_m1f[(size_t)r*128 + (c0-256)] = p;
                    }
                }
            } else {
                float d0 = 0.f, d1 = 0.f, d2 = 0.f;
#pragma unroll
                for (int j = 0; j < 4; j++) {
                    const int c0 = n0 + wn + j*8 + cpair;
                    float v0 = fmaxf(acc[i][j][half*2+0] + bias[c0],   0.f);
                    float v1 = fmaxf(acc[i][j][half*2+1] + bias[c0+1], 0.f);
                    d0 = fmaf(v0, Wo[c0*3+0], fmaf(v1, Wo[(c0+1)*3+0], d0));
                    d1 = fmaf(v0, Wo[c0*3+1], fmaf(v1, Wo[(c0+1)*3+1], d1));
                    d2 = fmaf(v0, Wo[c0*3+2], fmaf(v1, Wo[(c0+1)*3+2], d2));
                }
#pragma unroll
                for (int o = 1; o <= 2; o <<= 1) {
                    d0 += __shfl_xor_sync(0xffffffffu, d0, o);
                    d1 += __shfl_xor_sync(0xffffffffu, d1, o);
                    d2 += __shfl_xor_sync(0xffffffffu, d2, o);
                }
                if ((lane & 3) == 0) {
                    atomicAdd(&out[r*3+0], 0.3f * d0);
                    atomicAdd(&out[r*3+1], 0.3f * d1);
                    atomicAdd(&out[r*3+2], 0.3f * d2);
                }
            }
        }
    }
}

// --------------------------------- launch --------------------------------
extern "C" void kernel_launch(void* const* d_in, const int* in_sizes, int n_in,
                              void* d_out, int out_size)
{
    const float* tmpl  = (const float*)d_in[0];
    const float* surf  = (const float*)d_in[1];
    const float* gfeat = (const float*)d_in[2];
    const float* pfeat = (const float*)d_in[3];
    const float* W1 = (const float*)d_in[4];
    const float* b1 = (const float*)d_in[5];
    const float* W2 = (const float*)d_in[6];
    const float* b2 = (const float*)d_in[7];
    const float* Ws = (const float*)d_in[8];
    const float* bs = (const float*)d_in[9];
    const float* Wo = (const float*)d_in[10];
    const float* bo = (const float*)d_in[11];
    const float* M1 = (const float*)d_in[12];
    const float* mb1 = (const float*)d_in[13];
    const float* M2 = (const float*)d_in[14];
    const float* mb2 = (const float*)d_in[15];
    const float* M3 = (const float*)d_in[16];
    const float* mb3 = (const float*)d_in[17];
    float* out = (float*)d_out;

    // 1: fused KNN + all weight/global precompute
    front_kernel<<<FRONT_BLKS, 256>>>(tmpl, surf, Ws, Wo, W1, M1, b1, mb1,
                                      gfeat, bs, bo, W2);
    // 2: ni build + skip-dot store
    build_ni_kernel<<<NIB, 256>>>(tmpl, pfeat, out);
    // 3: GEMM1  [32768 x 288] @ [288 x 384]
    mma_gemm<0><<<dim3(NG1/64, ROWS/128), 256>>>(nullptr, nullptr, nullptr,
                                                 nullptr, nullptr, nullptr, nullptr);
    // 4: fused GEMM2a + disp head + gemm2b + mat head  <- profiled slot
    mma_gemm<1><<<dim3(5, ROWS/128), 256>>>(b2, Wo, out, M2, mb2, M3, mb3);
}